// round 9
// baseline (speedup 1.0000x reference)
#include <cuda_runtime.h>
#include <cstdint>

#define BATCH   16384
#define IN_DIM  1024
#define HID_DIM 2048
#define OUT_DIM 1024

// operand tile: 128 rows x 144B (hi k0..63 | lo k0..63 | 16B pad)
#define TILE      18432
#define TILE_U32  4608

// ------------------------------ scratch ------------------------------------
__device__ float    g_h [(size_t)BATCH * HID_DIM];
__device__ unsigned g_b1[(size_t)16 * 128 * TILE_U32];   // layer1 packed B images
__device__ unsigned g_b2[(size_t)8  * 256 * TILE_U32];   // layer2 packed B images
__device__ float    g_bias1[HID_DIM], g_bias2[OUT_DIM];
__device__ float    g_bpart[16][HID_DIM];
__device__ unsigned g_mk1[HID_DIM], g_xk1[HID_DIM];
__device__ unsigned g_mk2[HID_DIM], g_xk2[HID_DIM];
__device__ float    g_mn[HID_DIM],  g_sc[HID_DIM];
__device__ unsigned g_cm[2];                              // max|coeff| bits
__device__ float    g_qs1[3], g_qs2[3];                   // {qs, f1, f2}

// ---------------------------- helpers --------------------------------------
__device__ __forceinline__ unsigned fkey(float f) {
    unsigned u = __float_as_uint(f);
    return (u & 0x80000000u) ? ~u : (u | 0x80000000u);
}
__device__ __forceinline__ float funkey(unsigned u) {
    return __uint_as_float((u & 0x80000000u) ? (u ^ 0x80000000u) : ~u);
}
__device__ __forceinline__ void cp16(unsigned s, const void* g) {
    asm volatile("cp.async.cg.shared.global [%0], [%1], 16;" :: "r"(s), "l"(g) : "memory");
}
__device__ __forceinline__ void sts32(unsigned a, unsigned v) {
    asm volatile("st.shared.b32 [%0], %1;" :: "r"(a), "r"(v));
}
__device__ __forceinline__ void ldsm4(unsigned addr, unsigned* r) {
    asm volatile("ldmatrix.sync.aligned.m8n8.x4.shared.b16 {%0,%1,%2,%3}, [%4];"
                 : "=r"(r[0]), "=r"(r[1]), "=r"(r[2]), "=r"(r[3]) : "r"(addr));
}
__device__ __forceinline__ void mma_s8(int* c, const unsigned* a,
                                       unsigned b0, unsigned b1) {
    asm volatile(
        "mma.sync.aligned.m16n8k32.row.col.s32.s8.s8.s32 "
        "{%0,%1,%2,%3}, {%4,%5,%6,%7}, {%8,%9}, {%0,%1,%2,%3};"
        : "+r"(c[0]), "+r"(c[1]), "+r"(c[2]), "+r"(c[3])
        : "r"(a[0]), "r"(a[1]), "r"(a[2]), "r"(a[3]), "r"(b0), "r"(b1));
}
// bytes LSB->MSB = a0,a1,a2,a3
__device__ __forceinline__ unsigned pack4(int a0, int a1, int a2, int a3) {
    unsigned t, d;
    asm("cvt.pack.sat.s8.s32.b32 %0, %1, %2, %3;" : "=r"(t) : "r"(a3), "r"(a2), "r"(0u));
    asm("cvt.pack.sat.s8.s32.b32 %0, %1, %2, %3;" : "=r"(d) : "r"(a1), "r"(a0), "r"(t));
    return d;
}
// split q in [-8256,8256] into ah,al with q = 128*ah + al
__device__ __forceinline__ void qsplit(float v, float qscale, int& ah, int& al) {
    int q = __float2int_rn(v * qscale);
    ah = (q + 64) >> 7;
    al = q - (ah << 7);
}

// --------------------------- min/max kernels -------------------------------
__global__ void minmax_init(unsigned* mink, unsigned* maxk, int F) {
    int c = blockIdx.x * blockDim.x + threadIdx.x;
    if (c < F) { mink[c] = 0xFFFFFFFFu; maxk[c] = 0u; }
}
__global__ void colminmax(const float* __restrict__ X, int F, int chunk,
                          unsigned* mink, unsigned* maxk) {
    int c  = blockIdx.x * blockDim.x + threadIdx.x;
    int r0 = blockIdx.y * chunk;
    float lo =  3.402823466e38f, hi = -3.402823466e38f;
    const float* p = X + (size_t)r0 * F + c;
    for (int r = 0; r < chunk; ++r) {
        float v = p[(size_t)r * F];
        lo = fminf(lo, v); hi = fmaxf(hi, v);
    }
    atomicMin(&mink[c], fkey(lo));
    atomicMax(&maxk[c], fkey(hi));
}
__global__ void finalize_minmax(const unsigned* mink, const unsigned* maxk,
                                float* mn, float* sc, int F) {
    int c = blockIdx.x * blockDim.x + threadIdx.x;
    if (c < F) {
        float lo = funkey(mink[c]), hi = funkey(maxk[c]);
        mn[c] = lo; sc[c] = 2.0f / (hi - lo);
    }
}

// --------------------------- coeff max-abs ---------------------------------
__global__ void maxabs_init(unsigned* m) {
    if (threadIdx.x == 0 && blockIdx.x == 0) { m[0] = 0u; m[1] = 0u; }
}
__global__ void maxabs(const float4* __restrict__ p, int n4, unsigned* m) {
    int i = blockIdx.x * blockDim.x + threadIdx.x;
    float v = 0.0f;
    for (; i < n4; i += gridDim.x * blockDim.x) {
        float4 q = p[i];
        v = fmaxf(v, fmaxf(fmaxf(fabsf(q.x), fabsf(q.y)),
                           fmaxf(fabsf(q.z), fabsf(q.w))));
    }
    #pragma unroll
    for (int off = 16; off > 0; off >>= 1)
        v = fmaxf(v, __shfl_xor_sync(0xFFFFFFFFu, v, off));
    if ((threadIdx.x & 31) == 0) atomicMax(m, __float_as_uint(v));
}
__global__ void finalize_qs(const unsigned* m, float* q) {
    if (threadIdx.x == 0) {
        float cmax = __uint_as_float(m[0]);
        q[0] = 8192.0f / cmax;        // qs  (B quant scale)
        q[1] = cmax / 4096.0f;        // f1 = sB/64      (sB = cmax/64)
        q[2] = cmax / 524288.0f;      // f2 = sB/8192
    }
}

// ------------------------------ bias ---------------------------------------
__global__ void bias_part(const float* __restrict__ coeffs,
                          float* __restrict__ part, int F, int O) {
    int o  = blockIdx.x * blockDim.x + threadIdx.x;
    int i0 = blockIdx.y * 128;
    float s = 0.0f;
    #pragma unroll 4
    for (int i = 0; i < 128; ++i)
        s += coeffs[((size_t)(i0 + i) * O + o) * 9];
    part[blockIdx.y * HID_DIM + o] = s;
}
__global__ void bias_reduce(const float* __restrict__ part,
                            float* __restrict__ bias, int nparts, int O) {
    int o = blockIdx.x * blockDim.x + threadIdx.x;
    float s = 0.0f;
    for (int p = 0; p < nparts; ++p) s += part[p * HID_DIM + o];
    bias[o] = s;
}

// ------------------------------ B prep -------------------------------------
// coeffs [F,O,9] -> per (nblock, 8-feature chunk): 18432B image.
// row n: bytes 0..63 = bh(k), 64..127 = bl(k), k=(d-1)*8+il; 128..143 zero.
__global__ void prep_B(const float* __restrict__ coeffs,
                       unsigned* __restrict__ outB, int F, int O,
                       const float* __restrict__ qsp) {
    __shared__ float stag[8 * 128 * 9];         // [il][n][d]
    const float qs = __ldg(qsp);
    const int nb = blockIdx.x, c = blockIdx.y, tid = threadIdx.x;
    const float* src = coeffs + ((size_t)(c * 8) * O + (size_t)nb * 128) * 9;
    for (int idx = tid; idx < 9216; idx += 256) {
        int il = idx / 1152, rem = idx - il * 1152;       // rem = n*9 + d
        stag[idx] = src[(size_t)il * O * 9 + rem];
    }
    __syncthreads();
    const int nch = F / 8;
    unsigned* dst = outB + ((size_t)nb * nch + c) * TILE_U32;
    for (int j = tid; j < TILE_U32; j += 256) {
        int nn = j / 36;
        int c4 = (j - nn * 36) * 4;              // byte col 0..143
        unsigned v = 0;
        if (c4 < 128) {
            const int lo = (c4 >= 64) ? 1 : 0;
            const int kb = c4 - 64 * lo;
            int b[4];
            #pragma unroll
            for (int e = 0; e < 4; ++e) {
                int k  = kb + e;
                int d  = (k >> 3) + 1;
                int il = k & 7;
                int bh, bl;
                qsplit(stag[il * 1152 + nn * 9 + d], qs, bh, bl);
                b[e] = lo ? bl : bh;
            }
            v = pack4(b[0], b[1], b[2], b[3]);
        }
        dst[j] = v;
    }
}

// ------------------------ A-tile generation --------------------------------
__device__ __forceinline__ void gen_A(unsigned abase, int r, int h4, float4 xv,
                                      const float* __restrict__ mn,
                                      const float* __restrict__ sc, int f0) {
    float t[4], p[4], x2[4];
    float xs[4] = {xv.x, xv.y, xv.z, xv.w};
    #pragma unroll
    for (int fl = 0; fl < 4; ++fl) {
        int f = f0 + h4 + fl;
        float xn = (xs[fl] - __ldg(mn + f)) * __ldg(sc + f) - 1.0f;
        t[fl] = xn; p[fl] = 1.0f; x2[fl] = xn + xn;
    }
    unsigned base = abase + (unsigned)(r * 144 + h4);
    #pragma unroll
    for (int d = 1; d <= 8; ++d) {
        int ah[4], al[4];
        #pragma unroll
        for (int fl = 0; fl < 4; ++fl) {
            qsplit(t[fl], 8192.0f, ah[fl], al[fl]);
            float nt = fmaf(x2[fl], t[fl], -p[fl]);
            p[fl] = t[fl]; t[fl] = nt;
        }
        sts32(base + (d - 1) * 8,      pack4(ah[0], ah[1], ah[2], ah[3]));
        sts32(base + 64 + (d - 1) * 8, pack4(al[0], al[1], al[2], al[3]));
    }
}

// ------------------------- fused s8 mma GEMM -------------------------------
// C[128,128] per CTA = bias + sB*(acc1/64 + acc2/8192), acc over 8-feature
// chunks (K=64 = 2 k-blocks of 32). A double-buffered gen, B triple cp.async.
__global__ void __launch_bounds__(256, 1)
kan_mma(const float* __restrict__ X, const unsigned* __restrict__ gB,
        const float* __restrict__ mn, const float* __restrict__ sc,
        const float* __restrict__ bias, const float* __restrict__ qf,
        float* __restrict__ out, int F, int O,
        unsigned* mink2, unsigned* maxk2)
{
    extern __shared__ __align__(16) char smem[];
    const unsigned A_u = (unsigned)__cvta_generic_to_shared(smem);
    const unsigned B_u = A_u + 2 * TILE;

    const int tid  = threadIdx.x;
    const int wid  = tid >> 5;
    const int lane = tid & 31;
    const int brow0 = blockIdx.y * 128;
    const int oc0   = blockIdx.x * 128;
    const int nch   = F / 8;
    const unsigned* gb = gB + (size_t)blockIdx.x * nch * TILE_U32;

    const int wm = (wid >> 2) * 64;
    const int wn = (wid & 3) * 32;
    const int lrow = ((lane >> 3) & 1) * 8 + (lane & 7);
    const int lcolb = (lane >> 4) * 16;                    // byte col half
    unsigned offA[4], offB[2];
    #pragma unroll
    for (int i = 0; i < 4; ++i) offA[i] = (unsigned)((wm + i * 16 + lrow) * 144 + lcolb);
    #pragma unroll
    for (int t = 0; t < 2; ++t) offB[t] = (unsigned)((wn + t * 16 + lrow) * 144 + lcolb);

    int acc1[4][4][4], acc2[4][4][4];
    #pragma unroll
    for (int i = 0; i < 4; ++i)
        #pragma unroll
        for (int j = 0; j < 4; ++j)
            #pragma unroll
            for (int e = 0; e < 4; ++e) { acc1[i][j][e] = 0; acc2[i][j][e] = 0; }

    const int r  = tid >> 1;
    const int h4 = (tid & 1) << 2;

    // ---- prologue: B(0), B(1) in flight; A(0) generated
    for (int idx = tid; idx < 1152; idx += 256)
        cp16(B_u + idx * 16, (const char*)gb + (size_t)idx * 16);
    asm volatile("cp.async.commit_group;" ::: "memory");
    for (int idx = tid; idx < 1152; idx += 256)
        cp16(B_u + TILE + idx * 16, (const char*)(gb + TILE_U32) + (size_t)idx * 16);
    asm volatile("cp.async.commit_group;" ::: "memory");
    {
        float4 xv = *(const float4*)(X + (size_t)(brow0 + r) * F + h4);
        gen_A(A_u, r, h4, xv, mn, sc, 0);
    }
    asm volatile("cp.async.wait_group 1;" ::: "memory");
    __syncthreads();

    int bstage = 0;
    for (int c = 0; c < nch; ++c) {
        const unsigned Anow = A_u + ((unsigned)c & 1u) * TILE;
        const unsigned Bc   = B_u + (unsigned)bstage * TILE;

        // 1. issue B(c+2)
        const bool more = (c + 2 < nch);
        if (more) {
            int ns = bstage + 2; if (ns >= 3) ns -= 3;
            const char* gsrc = (const char*)(gb + (size_t)(c + 2) * TILE_U32);
            unsigned Bn = B_u + (unsigned)ns * TILE;
            for (int idx = tid; idx < 1152; idx += 256)
                cp16(Bn + idx * 16, gsrc + (size_t)idx * 16);
            asm volatile("cp.async.commit_group;" ::: "memory");
        }

        // 2. prefetch x for chunk c+1
        float4 xv = make_float4(0.f, 0.f, 0.f, 0.f);
        const int f0n = (c + 1) * 8;
        if (c + 1 < nch)
            xv = *(const float4*)(X + (size_t)(brow0 + r) * F + f0n + h4);

        // 3. MMA: 2 k-blocks of 32, 3 split passes each
        #pragma unroll
        for (int s = 0; s < 2; ++s) {
            const unsigned kh = (unsigned)(s * 32);
            unsigned ah[4][4], al[4][4], bh[2][4], bl[2][4];
            #pragma unroll
            for (int i = 0; i < 4; ++i) ldsm4(Anow + offA[i] + kh, ah[i]);
            #pragma unroll
            for (int t = 0; t < 2; ++t) ldsm4(Bc + offB[t] + kh, bh[t]);
            #pragma unroll
            for (int i = 0; i < 4; ++i)
                #pragma unroll
                for (int t = 0; t < 2; ++t)
                    #pragma unroll
                    for (int nb = 0; nb < 2; ++nb)
                        mma_s8(acc1[i][t * 2 + nb], ah[i], bh[t][nb], bh[t][nb + 2]);
            #pragma unroll
            for (int i = 0; i < 4; ++i) ldsm4(Anow + offA[i] + 64 + kh, al[i]);
            #pragma unroll
            for (int t = 0; t < 2; ++t) ldsm4(Bc + offB[t] + 64 + kh, bl[t]);
            #pragma unroll
            for (int i = 0; i < 4; ++i)
                #pragma unroll
                for (int t = 0; t < 2; ++t)
                    #pragma unroll
                    for (int nb = 0; nb < 2; ++nb)
                        mma_s8(acc2[i][t * 2 + nb], ah[i], bl[t][nb], bl[t][nb + 2]);
            #pragma unroll
            for (int i = 0; i < 4; ++i)
                #pragma unroll
                for (int t = 0; t < 2; ++t)
                    #pragma unroll
                    for (int nb = 0; nb < 2; ++nb)
                        mma_s8(acc2[i][t * 2 + nb], al[i], bh[t][nb], bh[t][nb + 2]);
        }

        // 4. expand A(c+1)
        if (c + 1 < nch)
            gen_A(A_u + ((unsigned)(c + 1) & 1u) * TILE, r, h4, xv, mn, sc, f0n);

        // 5. B(c+1) complete; A visible
        if (more) asm volatile("cp.async.wait_group 1;" ::: "memory");
        else      asm volatile("cp.async.wait_group 0;" ::: "memory");
        __syncthreads();

        if (++bstage >= 3) bstage -= 3;
    }

    // ---- epilogue: dequant + bias, store, fused next-layer min/max
    const float f1 = __ldg(qf + 1);
    const float f2 = __ldg(qf + 2);
    #pragma unroll
    for (int j = 0; j < 4; ++j) {
        const int col = oc0 + wn + j * 8 + (lane & 3) * 2;
        const float2 bv = *(const float2*)(bias + col);
        float mnE =  3.402823466e38f, mxE = -3.402823466e38f;
        float mnO =  3.402823466e38f, mxO = -3.402823466e38f;
        #pragma unroll
        for (int i = 0; i < 4; ++i) {
            const int row0 = brow0 + wm + i * 16 + (lane >> 2);
            float2 vlo, vhi;
            vlo.x = fmaf(f1, (float)acc1[i][j][0], fmaf(f2, (float)acc2[i][j][0], bv.x));
            vlo.y = fmaf(f1, (float)acc1[i][j][1], fmaf(f2, (float)acc2[i][j][1], bv.y));
            vhi.x = fmaf(f1, (float)acc1[i][j][2], fmaf(f2, (float)acc2[i][j][2], bv.x));
            vhi.y = fmaf(f1, (float)acc1[i][j][3], fmaf(f2, (float)acc2[i][j][3], bv.y));
            *(float2*)(out + (size_t)row0 * O + col)       = vlo;
            *(float2*)(out + (size_t)(row0 + 8) * O + col) = vhi;
            mnE = fminf(mnE, fminf(vlo.x, vhi.x));
            mxE = fmaxf(mxE, fmaxf(vlo.x, vhi.x));
            mnO = fminf(mnO, fminf(vlo.y, vhi.y));
            mxO = fmaxf(mxO, fmaxf(vlo.y, vhi.y));
        }
        if (mink2 != nullptr) {
            #pragma unroll
            for (int off = 4; off < 32; off <<= 1) {
                mnE = fminf(mnE, __shfl_xor_sync(0xFFFFFFFFu, mnE, off));
                mxE = fmaxf(mxE, __shfl_xor_sync(0xFFFFFFFFu, mxE, off));
                mnO = fminf(mnO, __shfl_xor_sync(0xFFFFFFFFu, mnO, off));
                mxO = fmaxf(mxO, __shfl_xor_sync(0xFFFFFFFFu, mxO, off));
            }
            if (lane < 4) {
                atomicMin(&mink2[col],     fkey(mnE));
                atomicMax(&maxk2[col],     fkey(mxE));
                atomicMin(&mink2[col + 1], fkey(mnO));
                atomicMax(&maxk2[col + 1], fkey(mxO));
            }
        }
    }
}

// ------------------------------ launcher -----------------------------------
extern "C" void kernel_launch(void* const* d_in, const int* in_sizes, int n_in,
                              void* d_out, int out_size) {
    const float* x  = (const float*)d_in[0];
    const float* c1 = (const float*)d_in[1];
    const float* c2 = (const float*)d_in[2];
    float* y = (float*)d_out;

    float *h, *mn, *sc, *bias1, *bias2, *bpart, *qs1, *qs2;
    unsigned *b1, *b2, *mk1, *xk1, *mk2, *xk2, *cm;
    cudaGetSymbolAddress((void**)&h,     g_h);
    cudaGetSymbolAddress((void**)&b1,    g_b1);
    cudaGetSymbolAddress((void**)&b2,    g_b2);
    cudaGetSymbolAddress((void**)&bias1, g_bias1);
    cudaGetSymbolAddress((void**)&bias2, g_bias2);
    cudaGetSymbolAddress((void**)&bpart, g_bpart);
    cudaGetSymbolAddress((void**)&mk1,   g_mk1);
    cudaGetSymbolAddress((void**)&xk1,   g_xk1);
    cudaGetSymbolAddress((void**)&mk2,   g_mk2);
    cudaGetSymbolAddress((void**)&xk2,   g_xk2);
    cudaGetSymbolAddress((void**)&mn,    g_mn);
    cudaGetSymbolAddress((void**)&sc,    g_sc);
    cudaGetSymbolAddress((void**)&cm,    g_cm);
    cudaGetSymbolAddress((void**)&qs1,   g_qs1);
    cudaGetSymbolAddress((void**)&qs2,   g_qs2);

    cudaFuncSetAttribute(kan_mma, cudaFuncAttributeMaxDynamicSharedMemorySize, 5 * TILE);

    // ---- quant scales from coeff max-abs
    maxabs_init<<<1, 32>>>(cm);
    maxabs<<<1024, 256>>>((const float4*)c1, IN_DIM  * HID_DIM * 9 / 4, cm);
    maxabs<<<1024, 256>>>((const float4*)c2, HID_DIM * OUT_DIM * 9 / 4, cm + 1);
    finalize_qs<<<1, 32>>>(cm,     qs1);
    finalize_qs<<<1, 32>>>(cm + 1, qs2);

    // ---- prep: packed int8 B images + exact d=0 biases
    prep_B<<<dim3(16, IN_DIM  / 8), 256>>>(c1, b1, IN_DIM,  HID_DIM, qs1);
    prep_B<<<dim3(8,  HID_DIM / 8), 256>>>(c2, b2, HID_DIM, OUT_DIM, qs2);
    bias_part<<<dim3(HID_DIM / 256, IN_DIM  / 128), 256>>>(c1, bpart, IN_DIM,  HID_DIM);
    bias_reduce<<<HID_DIM / 256, 256>>>(bpart, bias1, IN_DIM / 128, HID_DIM);
    bias_part<<<dim3(OUT_DIM / 256, HID_DIM / 128), 256>>>(c2, bpart, HID_DIM, OUT_DIM);
    bias_reduce<<<OUT_DIM / 256, 256>>>(bpart, bias2, HID_DIM / 128, OUT_DIM);

    // ---- layer 1 ----
    minmax_init<<<IN_DIM / 256, 256>>>(mk1, xk1, IN_DIM);
    colminmax<<<dim3(IN_DIM / 256, BATCH / 256), 256>>>(x, IN_DIM, 256, mk1, xk1);
    finalize_minmax<<<IN_DIM / 256, 256>>>(mk1, xk1, mn, sc, IN_DIM);
    minmax_init<<<HID_DIM / 256, 256>>>(mk2, xk2, HID_DIM);
    kan_mma<<<dim3(HID_DIM / 128, BATCH / 128), 256, 5 * TILE>>>(
        x, b1, mn, sc, bias1, qs1, h, IN_DIM, HID_DIM, mk2, xk2);

    // ---- layer 2 (minmax from fused epilogue) ----
    finalize_minmax<<<HID_DIM / 256, 256>>>(mk2, xk2, mn, sc, HID_DIM);
    kan_mma<<<dim3(OUT_DIM / 128, BATCH / 128), 256, 5 * TILE>>>(
        h, b2, mn, sc, bias2, qs2, y, HID_DIM, OUT_DIM, nullptr, nullptr);
}

// round 12
// speedup vs baseline: 6.4285x; 6.4285x over previous
#include <cuda_runtime.h>
#include <cuda_fp16.h>
#include <cstdint>

#define BATCH   16384
#define IN_DIM  1024
#define HID_DIM 2048
#define OUT_DIM 1024

#define SA        72                  // k-stride (fp16): 64 data + 8 pad, 144B rows
#define TILE      18432               // one operand tile: 128 x SA x 2B
#define TILE_U32  4608

// ------------------------------ scratch ------------------------------------
__device__ float    g_h [(size_t)BATCH * HID_DIM];
__device__ unsigned g_b1[(size_t)16 * 128 * TILE_U32];   // layer1 packed B images
__device__ unsigned g_b2[(size_t)8  * 256 * TILE_U32];   // layer2 packed B images
__device__ float    g_bias1[HID_DIM], g_bias2[OUT_DIM];
__device__ float    g_bpart[262144];                     // chunk-partial d=0 sums
__device__ unsigned g_mk1[HID_DIM], g_xk1[HID_DIM];      // layer1 input minmax
__device__ unsigned g_mk2[HID_DIM], g_xk2[HID_DIM];      // layer2 (fused) minmax
__device__ float    g_mn[HID_DIM],  g_sc[HID_DIM];

// ---------------------------- helpers --------------------------------------
__device__ __forceinline__ unsigned fkey(float f) {
    unsigned u = __float_as_uint(f);
    return (u & 0x80000000u) ? ~u : (u | 0x80000000u);
}
__device__ __forceinline__ float funkey(unsigned u) {
    return __uint_as_float((u & 0x80000000u) ? (u ^ 0x80000000u) : ~u);
}
__device__ __forceinline__ void cp16(unsigned s, const void* g) {
    asm volatile("cp.async.cg.shared.global [%0], [%1], 16;" :: "r"(s), "l"(g) : "memory");
}
__device__ __forceinline__ void ldsm4(unsigned addr, unsigned* r) {
    asm volatile("ldmatrix.sync.aligned.m8n8.x4.shared.b16 {%0,%1,%2,%3}, [%4];"
                 : "=r"(r[0]), "=r"(r[1]), "=r"(r[2]), "=r"(r[3]) : "r"(addr));
}
__device__ __forceinline__ void mma16816(float* c, const unsigned* a,
                                         unsigned b0, unsigned b1) {
    asm volatile(
        "mma.sync.aligned.m16n8k16.row.col.f32.f16.f16.f32 "
        "{%0,%1,%2,%3}, {%4,%5,%6,%7}, {%8,%9}, {%0,%1,%2,%3};"
        : "+f"(c[0]), "+f"(c[1]), "+f"(c[2]), "+f"(c[3])
        : "r"(a[0]), "r"(a[1]), "r"(a[2]), "r"(a[3]), "r"(b0), "r"(b1));
}

// --------------------------- min/max kernels -------------------------------
__global__ void minmax_init(unsigned* mink, unsigned* maxk, int F) {
    int c = blockIdx.x * blockDim.x + threadIdx.x;
    if (c < F) { mink[c] = 0xFFFFFFFFu; maxk[c] = 0u; }
}
__global__ void colminmax(const float* __restrict__ X, int F, int chunk,
                          unsigned* mink, unsigned* maxk) {
    int c  = blockIdx.x * blockDim.x + threadIdx.x;
    int r0 = blockIdx.y * chunk;
    float lo =  3.402823466e38f, hi = -3.402823466e38f;
    const float* p = X + (size_t)r0 * F + c;
    #pragma unroll 1
    for (int r = 0; r < chunk; r += 4) {            // 4 independent loads -> MLP 4
        float v0 = p[(size_t)(r + 0) * F];
        float v1 = p[(size_t)(r + 1) * F];
        float v2 = p[(size_t)(r + 2) * F];
        float v3 = p[(size_t)(r + 3) * F];
        lo = fminf(lo, fminf(fminf(v0, v1), fminf(v2, v3)));
        hi = fmaxf(hi, fmaxf(fmaxf(v0, v1), fmaxf(v2, v3)));
    }
    atomicMin(&mink[c], fkey(lo));
    atomicMax(&maxk[c], fkey(hi));
}
__global__ void finalize_minmax(const unsigned* mink, const unsigned* maxk,
                                float* mn, float* sc, int F) {
    int c = blockIdx.x * blockDim.x + threadIdx.x;
    if (c < F) {
        float lo = funkey(mink[c]), hi = funkey(maxk[c]);
        mn[c] = lo; sc[c] = 2.0f / (hi - lo);
    }
}

// ------------------------------ bias reduce --------------------------------
// bias[o] = sum over chunk partials (partials produced inside prep_B)
__global__ void bias_reduce(const float* __restrict__ part,
                            float* __restrict__ bias, int nparts, int O) {
    int o = blockIdx.x * blockDim.x + threadIdx.x;
    float s = 0.0f;
    for (int p = 0; p < nparts; ++p) s += part[(size_t)p * O + o];
    bias[o] = s;
}

// ------------------------------ B prep -------------------------------------
// coeffs [F,O,9] fp32 -> per (nblock, 8-feature chunk): 18432B smem image.
// row n (0..127), col k (0..71): k<64 -> fp16(coeffs[f0+(k&7), n0+n, (k>>3)+1]).
// Also emits the chunk's d=0 partial bias sums (reuses staged data).
__global__ void prep_B(const float* __restrict__ coeffs,
                       unsigned* __restrict__ outB,
                       float* __restrict__ part, int F, int O) {
    __shared__ float stag[8 * 128 * 9];         // [il][n][d]
    const int nb = blockIdx.x, c = blockIdx.y, tid = threadIdx.x;
    const float* src = coeffs + ((size_t)(c * 8) * O + (size_t)nb * 128) * 9;
    for (int idx = tid; idx < 9216; idx += 256) {
        int il = idx / 1152, rem = idx - il * 1152;       // rem = n*9 + d
        stag[idx] = src[(size_t)il * O * 9 + rem];
    }
    __syncthreads();
    const int nch = F / 8;
    unsigned* dst = outB + ((size_t)nb * nch + c) * TILE_U32;
    for (int j = tid; j < TILE_U32; j += 256) {
        int nn = j / 36;
        int k0 = (j - nn * 36) * 2;
        unsigned outv = 0;
        if (k0 < 64) {
            #pragma unroll
            for (int e = 0; e < 2; ++e) {
                int k  = k0 + e;
                int d  = (k >> 3) + 1;
                int il = k & 7;
                float v = stag[il * 1152 + nn * 9 + d];
                outv |= (unsigned)__half_as_ushort(__float2half_rn(v)) << (16 * e);
            }
        }
        dst[j] = outv;
    }
    // d=0 partial bias for this chunk's 128 outputs (fixed order, deterministic)
    if (tid < 128) {
        float s = 0.0f;
        #pragma unroll
        for (int il = 0; il < 8; ++il)
            s += stag[il * 1152 + tid * 9];
        part[(size_t)c * O + nb * 128 + tid] = s;
    }
}

// ------------------------- fused mma.sync GEMM -----------------------------
// C[128,128] per CTA = bias + sum over 8-feature chunks (K=64) of A(gen) x B.
// A double-buffered (gen overlapped with MMA), B triple-buffered cp.async.
// Optional fused per-column min/max atomics for the NEXT layer.
__global__ void __launch_bounds__(256, 2)
kan_mma(const float* __restrict__ X, const unsigned* __restrict__ gB,
        const float* __restrict__ mn, const float* __restrict__ sc,
        const float* __restrict__ bias, float* __restrict__ out,
        int F, int O, unsigned* mink2, unsigned* maxk2)
{
    extern __shared__ __align__(16) char smem[];
    const unsigned A_u = (unsigned)__cvta_generic_to_shared(smem);
    const unsigned B_u = A_u + 2 * TILE;                  // 3 stages after 2 A bufs
    __half* As = (__half*)smem;

    const int tid  = threadIdx.x;
    const int wid  = tid >> 5;
    const int lane = tid & 31;
    const int brow0 = blockIdx.y * 128;
    const int oc0   = blockIdx.x * 128;
    const int nch   = F / 8;
    const unsigned* gb = gB + (size_t)blockIdx.x * nch * TILE_U32;

    const int wm = (wid >> 2) * 64;
    const int wn = (wid & 3) * 32;
    const int lrow = ((lane >> 3) & 1) * 8 + (lane & 7);
    const int lcol = (lane >> 4) * 8;
    unsigned offA[4], offB[2];
    #pragma unroll
    for (int i = 0; i < 4; ++i) offA[i] = ((wm + i * 16 + lrow) * SA + lcol) * 2;
    #pragma unroll
    for (int t = 0; t < 2; ++t) offB[t] = ((wn + t * 16 + lrow) * SA + lcol) * 2;

    float acc[4][4][4];
    #pragma unroll
    for (int i = 0; i < 4; ++i)
        #pragma unroll
        for (int j = 0; j < 4; ++j)
            #pragma unroll
            for (int e = 0; e < 4; ++e) acc[i][j][e] = 0.0f;

    const int r  = tid >> 1;            // A-gen: row
    const int h4 = (tid & 1) << 2;      // A-gen: 4-feature half

    // ---- prologue: B(0), B(1) in flight; A(0) generated
    for (int idx = tid; idx < 1152; idx += 256)
        cp16(B_u + idx * 16, (const char*)gb + (size_t)idx * 16);
    asm volatile("cp.async.commit_group;" ::: "memory");
    for (int idx = tid; idx < 1152; idx += 256)
        cp16(B_u + TILE + idx * 16, (const char*)(gb + TILE_U32) + (size_t)idx * 16);
    asm volatile("cp.async.commit_group;" ::: "memory");
    {
        const float4 xv = *(const float4*)(X + (size_t)(brow0 + r) * F + h4);
        const float xs[4] = {xv.x, xv.y, xv.z, xv.w};
        unsigned* Arow = (unsigned*)(As + r * SA);
        #pragma unroll
        for (int p = 0; p < 2; ++p) {
            const int fl = h4 + 2 * p;
            float xa = (xs[2*p]   - __ldg(mn + fl))     * __ldg(sc + fl)     - 1.0f;
            float xb = (xs[2*p+1] - __ldg(mn + fl + 1)) * __ldg(sc + fl + 1) - 1.0f;
            float Ta = xa, Tb = xb, Pa = 1.0f, Pb = 1.0f;
            const float x2a = xa + xa, x2b = xb + xb;
            #pragma unroll
            for (int d = 1; d < 9; ++d) {
                Arow[(d - 1) * 4 + (fl >> 1)] =
                      (unsigned)__half_as_ushort(__float2half_rn(Ta))
                    | ((unsigned)__half_as_ushort(__float2half_rn(Tb)) << 16);
                float na = fmaf(x2a, Ta, -Pa);
                float nb = fmaf(x2b, Tb, -Pb);
                Pa = Ta; Pb = Tb; Ta = na; Tb = nb;
            }
        }
    }
    asm volatile("cp.async.wait_group 1;" ::: "memory");
    __syncthreads();

    int bstage = 0;                     // B stage of chunk c
    for (int c = 0; c < nch; ++c) {
        const unsigned Anow = A_u + ((unsigned)c & 1u) * TILE;
        const unsigned Bc   = B_u + (unsigned)bstage * TILE;

        // 1. issue B(c+2) into stage (bstage+2)%3
        const bool more = (c + 2 < nch);
        if (more) {
            int ns = bstage + 2; if (ns >= 3) ns -= 3;
            const char* gsrc = (const char*)(gb + (size_t)(c + 2) * TILE_U32);
            unsigned Bn = B_u + (unsigned)ns * TILE;
            for (int idx = tid; idx < 1152; idx += 256)
                cp16(Bn + idx * 16, gsrc + (size_t)idx * 16);
            asm volatile("cp.async.commit_group;" ::: "memory");
        }

        // 2. prefetch x for chunk c+1 (LDG latency overlaps MMAs below)
        float4 xv = make_float4(0.f, 0.f, 0.f, 0.f);
        const int f0n = (c + 1) * 8;
        if (c + 1 < nch)
            xv = *(const float4*)(X + (size_t)(brow0 + r) * F + f0n + h4);

        // 3. MMA: 4 slabs of K=16
        #pragma unroll
        for (int s = 0; s < 4; ++s) {
            const unsigned kh = (unsigned)(s * 32);
            unsigned a[4][4], b[2][4];
            #pragma unroll
            for (int i = 0; i < 4; ++i) ldsm4(Anow + offA[i] + kh, a[i]);
            #pragma unroll
            for (int t = 0; t < 2; ++t) ldsm4(Bc + offB[t] + kh, b[t]);
            #pragma unroll
            for (int i = 0; i < 4; ++i)
                #pragma unroll
                for (int t = 0; t < 2; ++t)
                    #pragma unroll
                    for (int nb = 0; nb < 2; ++nb)
                        mma16816(acc[i][t * 2 + nb], a[i], b[t][nb], b[t][nb + 2]);
        }

        // 4. expand A(c+1) into the other A buffer (tensor-shadow work)
        if (c + 1 < nch) {
            const float xs[4] = {xv.x, xv.y, xv.z, xv.w};
            unsigned* Arow = (unsigned*)(As + (((c + 1) & 1) * TILE / 2) + r * SA);
            #pragma unroll
            for (int p = 0; p < 2; ++p) {
                const int fl = h4 + 2 * p;
                const int f  = f0n + fl;
                float xa = (xs[2*p]   - __ldg(mn + f))     * __ldg(sc + f)     - 1.0f;
                float xb = (xs[2*p+1] - __ldg(mn + f + 1)) * __ldg(sc + f + 1) - 1.0f;
                float Ta = xa, Tb = xb, Pa = 1.0f, Pb = 1.0f;
                const float x2a = xa + xa, x2b = xb + xb;
                #pragma unroll
                for (int d = 1; d < 9; ++d) {
                    Arow[(d - 1) * 4 + (fl >> 1)] =
                          (unsigned)__half_as_ushort(__float2half_rn(Ta))
                        | ((unsigned)__half_as_ushort(__float2half_rn(Tb)) << 16);
                    float na = fmaf(x2a, Ta, -Pa);
                    float nb = fmaf(x2b, Tb, -Pb);
                    Pa = Ta; Pb = Tb; Ta = na; Tb = nb;
                }
            }
        }

        // 5. B(c+1) complete; everything visible
        if (more) asm volatile("cp.async.wait_group 1;" ::: "memory");
        else      asm volatile("cp.async.wait_group 0;" ::: "memory");
        __syncthreads();

        if (++bstage >= 3) bstage -= 3;
    }

    // ---- epilogue: + bias, store, fused next-layer column min/max
    #pragma unroll
    for (int j = 0; j < 4; ++j) {
        const int col = oc0 + wn + j * 8 + (lane & 3) * 2;
        const float2 bv = *(const float2*)(bias + col);
        float mnE =  3.402823466e38f, mxE = -3.402823466e38f;
        float mnO =  3.402823466e38f, mxO = -3.402823466e38f;
        #pragma unroll
        for (int i = 0; i < 4; ++i) {
            const int row0 = brow0 + wm + i * 16 + (lane >> 2);
            float2 vlo = {acc[i][j][0] + bv.x, acc[i][j][1] + bv.y};
            float2 vhi = {acc[i][j][2] + bv.x, acc[i][j][3] + bv.y};
            *(float2*)(out + (size_t)row0 * O + col)       = vlo;
            *(float2*)(out + (size_t)(row0 + 8) * O + col) = vhi;
            mnE = fminf(mnE, fminf(vlo.x, vhi.x));
            mxE = fmaxf(mxE, fmaxf(vlo.x, vhi.x));
            mnO = fminf(mnO, fminf(vlo.y, vhi.y));
            mxO = fmaxf(mxO, fmaxf(vlo.y, vhi.y));
        }
        if (mink2 != nullptr) {
            #pragma unroll
            for (int off = 4; off < 32; off <<= 1) {
                mnE = fminf(mnE, __shfl_xor_sync(0xFFFFFFFFu, mnE, off));
                mxE = fmaxf(mxE, __shfl_xor_sync(0xFFFFFFFFu, mxE, off));
                mnO = fminf(mnO, __shfl_xor_sync(0xFFFFFFFFu, mnO, off));
                mxO = fmaxf(mxO, __shfl_xor_sync(0xFFFFFFFFu, mxO, off));
            }
            if (lane < 4) {
                atomicMin(&mink2[col],     fkey(mnE));
                atomicMax(&maxk2[col],     fkey(mxE));
                atomicMin(&mink2[col + 1], fkey(mnO));
                atomicMax(&maxk2[col + 1], fkey(mxO));
            }
        }
    }
}

// ------------------------------ launcher -----------------------------------
extern "C" void kernel_launch(void* const* d_in, const int* in_sizes, int n_in,
                              void* d_out, int out_size) {
    const float* x  = (const float*)d_in[0];
    const float* c1 = (const float*)d_in[1];
    const float* c2 = (const float*)d_in[2];
    float* y = (float*)d_out;

    float *h, *mn, *sc, *bias1, *bias2, *bpart;
    unsigned *b1, *b2, *mk1, *xk1, *mk2, *xk2;
    cudaGetSymbolAddress((void**)&h,     g_h);
    cudaGetSymbolAddress((void**)&b1,    g_b1);
    cudaGetSymbolAddress((void**)&b2,    g_b2);
    cudaGetSymbolAddress((void**)&bias1, g_bias1);
    cudaGetSymbolAddress((void**)&bias2, g_bias2);
    cudaGetSymbolAddress((void**)&bpart, g_bpart);
    cudaGetSymbolAddress((void**)&mk1,   g_mk1);
    cudaGetSymbolAddress((void**)&xk1,   g_xk1);
    cudaGetSymbolAddress((void**)&mk2,   g_mk2);
    cudaGetSymbolAddress((void**)&xk2,   g_xk2);
    cudaGetSymbolAddress((void**)&mn,    g_mn);
    cudaGetSymbolAddress((void**)&sc,    g_sc);

    cudaFuncSetAttribute(kan_mma, cudaFuncAttributeMaxDynamicSharedMemorySize, 5 * TILE);

    // ---- prep: packed B images (+fused d=0 partials) and bias reductions
    prep_B<<<dim3(16, IN_DIM  / 8), 256>>>(c1, b1, bpart, IN_DIM, HID_DIM);
    bias_reduce<<<HID_DIM / 256, 256>>>(bpart, bias1, IN_DIM / 8, HID_DIM);
    prep_B<<<dim3(8,  HID_DIM / 8), 256>>>(c2, b2, bpart, HID_DIM, OUT_DIM);
    bias_reduce<<<OUT_DIM / 256, 256>>>(bpart, bias2, HID_DIM / 8, OUT_DIM);

    // ---- layer 1 ----
    minmax_init<<<IN_DIM / 256, 256>>>(mk1, xk1, IN_DIM);
    colminmax<<<dim3(IN_DIM / 256, BATCH / 256), 256>>>(x, IN_DIM, 256, mk1, xk1);
    finalize_minmax<<<IN_DIM / 256, 256>>>(mk1, xk1, mn, sc, IN_DIM);
    minmax_init<<<HID_DIM / 256, 256>>>(mk2, xk2, HID_DIM);   // for fused epilogue
    kan_mma<<<dim3(HID_DIM / 128, BATCH / 128), 256, 5 * TILE>>>(
        x, b1, mn, sc, bias1, h, IN_DIM, HID_DIM, mk2, xk2);

    // ---- layer 2 (minmax came from layer-1 epilogue) ----
    finalize_minmax<<<HID_DIM / 256, 256>>>(mk2, xk2, mn, sc, HID_DIM);
    kan_mma<<<dim3(OUT_DIM / 128, BATCH / 128), 256, 5 * TILE>>>(
        h, b2, mn, sc, bias2, y, HID_DIM, OUT_DIM, nullptr, nullptr);
}

// round 15
// speedup vs baseline: 6.4361x; 1.0012x over previous
#include <cuda_runtime.h>
#include <cuda_fp16.h>
#include <cstdint>

#define BATCH   16384
#define IN_DIM  1024
#define HID_DIM 2048
#define OUT_DIM 1024

#define SA        72                  // k-stride (fp16): 64 data + 8 pad, 144B rows
#define TILE      18432               // one operand tile: 128 x SA x 2B
#define TILE_U32  4608

// ------------------------------ scratch ------------------------------------
__device__ float    g_h [(size_t)BATCH * HID_DIM];
__device__ unsigned g_b1[(size_t)16 * 128 * TILE_U32];   // layer1 packed B images
__device__ unsigned g_b2[(size_t)8  * 256 * TILE_U32];   // layer2 packed B images
__device__ float    g_bias1[HID_DIM], g_bias2[OUT_DIM];
__device__ float    g_bpart[262144];                     // chunk-partial d=0 sums
__device__ unsigned g_mk1[HID_DIM], g_xk1[HID_DIM];      // layer1 input minmax
__device__ unsigned g_mk2[HID_DIM], g_xk2[HID_DIM];      // layer2 (fused) minmax
__device__ float    g_mn[HID_DIM],  g_sc[HID_DIM];

// ---------------------------- helpers --------------------------------------
__device__ __forceinline__ unsigned fkey(float f) {
    unsigned u = __float_as_uint(f);
    return (u & 0x80000000u) ? ~u : (u | 0x80000000u);
}
__device__ __forceinline__ float funkey(unsigned u) {
    return __uint_as_float((u & 0x80000000u) ? (u ^ 0x80000000u) : ~u);
}
__device__ __forceinline__ void cp16(unsigned s, const void* g) {
    asm volatile("cp.async.cg.shared.global [%0], [%1], 16;" :: "r"(s), "l"(g) : "memory");
}
__device__ __forceinline__ void ldsm4(unsigned addr, unsigned* r) {
    asm volatile("ldmatrix.sync.aligned.m8n8.x4.shared.b16 {%0,%1,%2,%3}, [%4];"
                 : "=r"(r[0]), "=r"(r[1]), "=r"(r[2]), "=r"(r[3]) : "r"(addr));
}
__device__ __forceinline__ void mma16816(float* c, const unsigned* a,
                                         unsigned b0, unsigned b1) {
    asm volatile(
        "mma.sync.aligned.m16n8k16.row.col.f32.f16.f16.f32 "
        "{%0,%1,%2,%3}, {%4,%5,%6,%7}, {%8,%9}, {%0,%1,%2,%3};"
        : "+f"(c[0]), "+f"(c[1]), "+f"(c[2]), "+f"(c[3])
        : "r"(a[0]), "r"(a[1]), "r"(a[2]), "r"(a[3]), "r"(b0), "r"(b1));
}

// --------------------------- min/max kernels -------------------------------
__global__ void minmax_init(unsigned* mink, unsigned* maxk, int F) {
    int c = blockIdx.x * blockDim.x + threadIdx.x;
    if (c < F) { mink[c] = 0xFFFFFFFFu; maxk[c] = 0u; }
}
__global__ void colminmax(const float* __restrict__ X, int F, int chunk,
                          unsigned* mink, unsigned* maxk) {
    int c  = blockIdx.x * blockDim.x + threadIdx.x;
    int r0 = blockIdx.y * chunk;
    float lo =  3.402823466e38f, hi = -3.402823466e38f;
    const float* p = X + (size_t)r0 * F + c;
    #pragma unroll 1
    for (int r = 0; r < chunk; r += 8) {            // 8 independent loads -> MLP 8
        float v0 = p[(size_t)(r + 0) * F];
        float v1 = p[(size_t)(r + 1) * F];
        float v2 = p[(size_t)(r + 2) * F];
        float v3 = p[(size_t)(r + 3) * F];
        float v4 = p[(size_t)(r + 4) * F];
        float v5 = p[(size_t)(r + 5) * F];
        float v6 = p[(size_t)(r + 6) * F];
        float v7 = p[(size_t)(r + 7) * F];
        lo = fminf(lo, fminf(fminf(fminf(v0, v1), fminf(v2, v3)),
                             fminf(fminf(v4, v5), fminf(v6, v7))));
        hi = fmaxf(hi, fmaxf(fmaxf(fmaxf(v0, v1), fmaxf(v2, v3)),
                             fmaxf(fmaxf(v4, v5), fmaxf(v6, v7))));
    }
    atomicMin(&mink[c], fkey(lo));
    atomicMax(&maxk[c], fkey(hi));
}
__global__ void finalize_minmax(const unsigned* mink, const unsigned* maxk,
                                float* mn, float* sc, int F) {
    int c = blockIdx.x * blockDim.x + threadIdx.x;
    if (c < F) {
        float lo = funkey(mink[c]), hi = funkey(maxk[c]);
        mn[c] = lo; sc[c] = 2.0f / (hi - lo);
    }
}

// ------------------------------ bias reduce --------------------------------
// bias[o] = sum over chunk partials (partials produced inside prep_B)
__global__ void bias_reduce(const float* __restrict__ part,
                            float* __restrict__ bias, int nparts, int O) {
    int o = blockIdx.x * blockDim.x + threadIdx.x;
    float s0 = 0.0f, s1 = 0.0f, s2 = 0.0f, s3 = 0.0f;
    #pragma unroll 1
    for (int p = 0; p < nparts; p += 4) {           // 4 independent chains -> MLP 4
        s0 += part[(size_t)(p + 0) * O + o];
        s1 += part[(size_t)(p + 1) * O + o];
        s2 += part[(size_t)(p + 2) * O + o];
        s3 += part[(size_t)(p + 3) * O + o];
    }
    bias[o] = (s0 + s1) + (s2 + s3);
}

// ------------------------------ B prep -------------------------------------
// coeffs [F,O,9] fp32 -> per (nblock, 8-feature chunk): 18432B smem image.
// row n (0..127), col k (0..71): k<64 -> fp16(coeffs[f0+(k&7), n0+n, (k>>3)+1]).
// Also emits the chunk's d=0 partial bias sums (reuses staged data).
__global__ void prep_B(const float* __restrict__ coeffs,
                       unsigned* __restrict__ outB,
                       float* __restrict__ part, int F, int O) {
    __shared__ __align__(16) float stag[8 * 128 * 9];   // [il][n][d]
    const int nb = blockIdx.x, c = blockIdx.y, tid = threadIdx.x;
    const float* src = coeffs + ((size_t)(c * 8) * O + (size_t)nb * 128) * 9;
    // per-il blocks are 1152 contiguous floats and 16B-aligned -> float4 copy
    for (int idx4 = tid; idx4 < 2304; idx4 += 256) {
        int il = idx4 / 288, rem4 = idx4 - il * 288;
        reinterpret_cast<float4*>(stag)[idx4] =
            *reinterpret_cast<const float4*>(src + (size_t)il * O * 9 + rem4 * 4);
    }
    __syncthreads();
    const int nch = F / 8;
    unsigned* dst = outB + ((size_t)nb * nch + c) * TILE_U32;
    for (int j = tid; j < TILE_U32; j += 256) {
        int nn = j / 36;
        int k0 = (j - nn * 36) * 2;
        unsigned outv = 0;
        if (k0 < 64) {
            #pragma unroll
            for (int e = 0; e < 2; ++e) {
                int k  = k0 + e;
                int d  = (k >> 3) + 1;
                int il = k & 7;
                float v = stag[il * 1152 + nn * 9 + d];
                outv |= (unsigned)__half_as_ushort(__float2half_rn(v)) << (16 * e);
            }
        }
        dst[j] = outv;
    }
    // d=0 partial bias for this chunk's 128 outputs (fixed order, deterministic)
    if (tid < 128) {
        float s = 0.0f;
        #pragma unroll
        for (int il = 0; il < 8; ++il)
            s += stag[il * 1152 + tid * 9];
        part[(size_t)c * O + nb * 128 + tid] = s;
    }
}

// ------------------------- fused mma.sync GEMM -----------------------------
// C[128,128] per CTA = bias + sum over 8-feature chunks (K=64) of A(gen) x B.
// A double-buffered (gen overlapped with MMA), B triple-buffered cp.async.
// Optional fused per-column min/max atomics for the NEXT layer.
__global__ void __launch_bounds__(256, 2)
kan_mma(const float* __restrict__ X, const unsigned* __restrict__ gB,
        const float* __restrict__ mn, const float* __restrict__ sc,
        const float* __restrict__ bias, float* __restrict__ out,
        int F, int O, unsigned* mink2, unsigned* maxk2)
{
    extern __shared__ __align__(16) char smem[];
    const unsigned A_u = (unsigned)__cvta_generic_to_shared(smem);
    const unsigned B_u = A_u + 2 * TILE;                  // 3 stages after 2 A bufs
    __half* As = (__half*)smem;

    const int tid  = threadIdx.x;
    const int wid  = tid >> 5;
    const int lane = tid & 31;
    const int brow0 = blockIdx.y * 128;
    const int oc0   = blockIdx.x * 128;
    const int nch   = F / 8;
    const unsigned* gb = gB + (size_t)blockIdx.x * nch * TILE_U32;

    const int wm = (wid >> 2) * 64;
    const int wn = (wid & 3) * 32;
    const int lrow = ((lane >> 3) & 1) * 8 + (lane & 7);
    const int lcol = (lane >> 4) * 8;
    unsigned offA[4], offB[2];
    #pragma unroll
    for (int i = 0; i < 4; ++i) offA[i] = ((wm + i * 16 + lrow) * SA + lcol) * 2;
    #pragma unroll
    for (int t = 0; t < 2; ++t) offB[t] = ((wn + t * 16 + lrow) * SA + lcol) * 2;

    float acc[4][4][4];
    #pragma unroll
    for (int i = 0; i < 4; ++i)
        #pragma unroll
        for (int j = 0; j < 4; ++j)
            #pragma unroll
            for (int e = 0; e < 4; ++e) acc[i][j][e] = 0.0f;

    const int r  = tid >> 1;            // A-gen: row
    const int h4 = (tid & 1) << 2;      // A-gen: 4-feature half

    // ---- prologue: B(0), B(1) in flight; A(0) generated
    for (int idx = tid; idx < 1152; idx += 256)
        cp16(B_u + idx * 16, (const char*)gb + (size_t)idx * 16);
    asm volatile("cp.async.commit_group;" ::: "memory");
    for (int idx = tid; idx < 1152; idx += 256)
        cp16(B_u + TILE + idx * 16, (const char*)(gb + TILE_U32) + (size_t)idx * 16);
    asm volatile("cp.async.commit_group;" ::: "memory");
    {
        const float4 xv = *(const float4*)(X + (size_t)(brow0 + r) * F + h4);
        const float xs[4] = {xv.x, xv.y, xv.z, xv.w};
        unsigned* Arow = (unsigned*)(As + r * SA);
        #pragma unroll
        for (int p = 0; p < 2; ++p) {
            const int fl = h4 + 2 * p;
            float xa = (xs[2*p]   - __ldg(mn + fl))     * __ldg(sc + fl)     - 1.0f;
            float xb = (xs[2*p+1] - __ldg(mn + fl + 1)) * __ldg(sc + fl + 1) - 1.0f;
            float Ta = xa, Tb = xb, Pa = 1.0f, Pb = 1.0f;
            const float x2a = xa + xa, x2b = xb + xb;
            #pragma unroll
            for (int d = 1; d < 9; ++d) {
                Arow[(d - 1) * 4 + (fl >> 1)] =
                      (unsigned)__half_as_ushort(__float2half_rn(Ta))
                    | ((unsigned)__half_as_ushort(__float2half_rn(Tb)) << 16);
                float na = fmaf(x2a, Ta, -Pa);
                float nb = fmaf(x2b, Tb, -Pb);
                Pa = Ta; Pb = Tb; Ta = na; Tb = nb;
            }
        }
    }
    asm volatile("cp.async.wait_group 1;" ::: "memory");
    __syncthreads();

    int bstage = 0;                     // B stage of chunk c
    for (int c = 0; c < nch; ++c) {
        const unsigned Anow = A_u + ((unsigned)c & 1u) * TILE;
        const unsigned Bc   = B_u + (unsigned)bstage * TILE;

        // 1. issue B(c+2) into stage (bstage+2)%3
        const bool more = (c + 2 < nch);
        if (more) {
            int ns = bstage + 2; if (ns >= 3) ns -= 3;
            const char* gsrc = (const char*)(gb + (size_t)(c + 2) * TILE_U32);
            unsigned Bn = B_u + (unsigned)ns * TILE;
            for (int idx = tid; idx < 1152; idx += 256)
                cp16(Bn + idx * 16, gsrc + (size_t)idx * 16);
            asm volatile("cp.async.commit_group;" ::: "memory");
        }

        // 2. prefetch x for chunk c+1 (LDG latency overlaps MMAs below)
        float4 xv = make_float4(0.f, 0.f, 0.f, 0.f);
        const int f0n = (c + 1) * 8;
        if (c + 1 < nch)
            xv = *(const float4*)(X + (size_t)(brow0 + r) * F + f0n + h4);

        // 3. MMA: 4 slabs of K=16
        #pragma unroll
        for (int s = 0; s < 4; ++s) {
            const unsigned kh = (unsigned)(s * 32);
            unsigned a[4][4], b[2][4];
            #pragma unroll
            for (int i = 0; i < 4; ++i) ldsm4(Anow + offA[i] + kh, a[i]);
            #pragma unroll
            for (int t = 0; t < 2; ++t) ldsm4(Bc + offB[t] + kh, b[t]);
            #pragma unroll
            for (int i = 0; i < 4; ++i)
                #pragma unroll
                for (int t = 0; t < 2; ++t)
                    #pragma unroll
                    for (int nb = 0; nb < 2; ++nb)
                        mma16816(acc[i][t * 2 + nb], a[i], b[t][nb], b[t][nb + 2]);
        }

        // 4. expand A(c+1) into the other A buffer (tensor-shadow work)
        if (c + 1 < nch) {
            const float xs[4] = {xv.x, xv.y, xv.z, xv.w};
            unsigned* Arow = (unsigned*)(As + (((c + 1) & 1) * TILE / 2) + r * SA);
            #pragma unroll
            for (int p = 0; p < 2; ++p) {
                const int fl = h4 + 2 * p;
                const int f  = f0n + fl;
                float xa = (xs[2*p]   - __ldg(mn + f))     * __ldg(sc + f)     - 1.0f;
                float xb = (xs[2*p+1] - __ldg(mn + f + 1)) * __ldg(sc + f + 1) - 1.0f;
                float Ta = xa, Tb = xb, Pa = 1.0f, Pb = 1.0f;
                const float x2a = xa + xa, x2b = xb + xb;
                #pragma unroll
                for (int d = 1; d < 9; ++d) {
                    Arow[(d - 1) * 4 + (fl >> 1)] =
                          (unsigned)__half_as_ushort(__float2half_rn(Ta))
                        | ((unsigned)__half_as_ushort(__float2half_rn(Tb)) << 16);
                    float na = fmaf(x2a, Ta, -Pa);
                    float nb = fmaf(x2b, Tb, -Pb);
                    Pa = Ta; Pb = Tb; Ta = na; Tb = nb;
                }
            }
        }

        // 5. B(c+1) complete; everything visible
        if (more) asm volatile("cp.async.wait_group 1;" ::: "memory");
        else      asm volatile("cp.async.wait_group 0;" ::: "memory");
        __syncthreads();

        if (++bstage >= 3) bstage -= 3;
    }

    // ---- epilogue: + bias, store, fused next-layer column min/max
    #pragma unroll
    for (int j = 0; j < 4; ++j) {
        const int col = oc0 + wn + j * 8 + (lane & 3) * 2;
        const float2 bv = *(const float2*)(bias + col);
        float mnE =  3.402823466e38f, mxE = -3.402823466e38f;
        float mnO =  3.402823466e38f, mxO = -3.402823466e38f;
        #pragma unroll
        for (int i = 0; i < 4; ++i) {
            const int row0 = brow0 + wm + i * 16 + (lane >> 2);
            float2 vlo = {acc[i][j][0] + bv.x, acc[i][j][1] + bv.y};
            float2 vhi = {acc[i][j][2] + bv.x, acc[i][j][3] + bv.y};
            *(float2*)(out + (size_t)row0 * O + col)       = vlo;
            *(float2*)(out + (size_t)(row0 + 8) * O + col) = vhi;
            mnE = fminf(mnE, fminf(vlo.x, vhi.x));
            mxE = fmaxf(mxE, fmaxf(vlo.x, vhi.x));
            mnO = fminf(mnO, fminf(vlo.y, vhi.y));
            mxO = fmaxf(mxO, fmaxf(vlo.y, vhi.y));
        }
        if (mink2 != nullptr) {
            #pragma unroll
            for (int off = 4; off < 32; off <<= 1) {
                mnE = fminf(mnE, __shfl_xor_sync(0xFFFFFFFFu, mnE, off));
                mxE = fmaxf(mxE, __shfl_xor_sync(0xFFFFFFFFu, mxE, off));
                mnO = fminf(mnO, __shfl_xor_sync(0xFFFFFFFFu, mnO, off));
                mxO = fmaxf(mxO, __shfl_xor_sync(0xFFFFFFFFu, mxO, off));
            }
            if (lane < 4) {
                atomicMin(&mink2[col],     fkey(mnE));
                atomicMax(&maxk2[col],     fkey(mxE));
                atomicMin(&mink2[col + 1], fkey(mnO));
                atomicMax(&maxk2[col + 1], fkey(mxO));
            }
        }
    }
}

// ------------------------------ launcher -----------------------------------
extern "C" void kernel_launch(void* const* d_in, const int* in_sizes, int n_in,
                              void* d_out, int out_size) {
    const float* x  = (const float*)d_in[0];
    const float* c1 = (const float*)d_in[1];
    const float* c2 = (const float*)d_in[2];
    float* y = (float*)d_out;

    float *h, *mn, *sc, *bias1, *bias2, *bpart;
    unsigned *b1, *b2, *mk1, *xk1, *mk2, *xk2;
    cudaGetSymbolAddress((void**)&h,     g_h);
    cudaGetSymbolAddress((void**)&b1,    g_b1);
    cudaGetSymbolAddress((void**)&b2,    g_b2);
    cudaGetSymbolAddress((void**)&bias1, g_bias1);
    cudaGetSymbolAddress((void**)&bias2, g_bias2);
    cudaGetSymbolAddress((void**)&bpart, g_bpart);
    cudaGetSymbolAddress((void**)&mk1,   g_mk1);
    cudaGetSymbolAddress((void**)&xk1,   g_xk1);
    cudaGetSymbolAddress((void**)&mk2,   g_mk2);
    cudaGetSymbolAddress((void**)&xk2,   g_xk2);
    cudaGetSymbolAddress((void**)&mn,    g_mn);
    cudaGetSymbolAddress((void**)&sc,    g_sc);

    cudaFuncSetAttribute(kan_mma, cudaFuncAttributeMaxDynamicSharedMemorySize, 5 * TILE);

    // ---- prep: packed B images (+fused d=0 partials) and bias reductions
    prep_B<<<dim3(16, IN_DIM  / 8), 256>>>(c1, b1, bpart, IN_DIM, HID_DIM);
    bias_reduce<<<HID_DIM / 256, 256>>>(bpart, bias1, IN_DIM / 8, HID_DIM);
    prep_B<<<dim3(8,  HID_DIM / 8), 256>>>(c2, b2, bpart, HID_DIM, OUT_DIM);
    bias_reduce<<<OUT_DIM / 256, 256>>>(bpart, bias2, HID_DIM / 8, OUT_DIM);

    // ---- layer 1 ----
    minmax_init<<<IN_DIM / 256, 256>>>(mk1, xk1, IN_DIM);
    colminmax<<<dim3(IN_DIM / 256, BATCH / 256), 256>>>(x, IN_DIM, 256, mk1, xk1);
    finalize_minmax<<<IN_DIM / 256, 256>>>(mk1, xk1, mn, sc, IN_DIM);
    minmax_init<<<HID_DIM / 256, 256>>>(mk2, xk2, HID_DIM);   // for fused epilogue
    kan_mma<<<dim3(HID_DIM / 128, BATCH / 128), 256, 5 * TILE>>>(
        x, b1, mn, sc, bias1, h, IN_DIM, HID_DIM, mk2, xk2);

    // ---- layer 2 (minmax came from layer-1 epilogue) ----
    finalize_minmax<<<HID_DIM / 256, 256>>>(mk2, xk2, mn, sc, HID_DIM);
    kan_mma<<<dim3(OUT_DIM / 128, BATCH / 128), 256, 5 * TILE>>>(
        h, b2, mn, sc, bias2, y, HID_DIM, OUT_DIM, nullptr, nullptr);
}

// round 16
// speedup vs baseline: 6.4893x; 1.0083x over previous
#include <cuda_runtime.h>
#include <cuda_fp16.h>
#include <cstdint>

#define BATCH   16384
#define IN_DIM  1024
#define HID_DIM 2048
#define OUT_DIM 1024

#define SA        72                  // k-stride (fp16): 64 data + 8 pad, 144B rows
#define TILE      18432               // one operand tile: 128 x SA x 2B
#define TILE_U32  4608

// ------------------------------ scratch ------------------------------------
__device__ float    g_h [(size_t)BATCH * HID_DIM];
__device__ unsigned g_b1[(size_t)16 * 128 * TILE_U32];   // layer1 packed B images
__device__ unsigned g_b2[(size_t)8  * 256 * TILE_U32];   // layer2 packed B images
__device__ float    g_bias1[HID_DIM], g_bias2[OUT_DIM];
__device__ float    g_bpart[262144];                     // chunk-partial d=0 sums
__device__ unsigned g_mk1[HID_DIM], g_xk1[HID_DIM];      // layer1 input minmax
__device__ unsigned g_mk2[HID_DIM], g_xk2[HID_DIM];      // layer2 (fused) minmax
__device__ float    g_mn[HID_DIM],  g_sc[HID_DIM];

// ---------------------------- helpers --------------------------------------
__device__ __forceinline__ unsigned fkey(float f) {
    unsigned u = __float_as_uint(f);
    return (u & 0x80000000u) ? ~u : (u | 0x80000000u);
}
__device__ __forceinline__ float funkey(unsigned u) {
    return __uint_as_float((u & 0x80000000u) ? (u ^ 0x80000000u) : ~u);
}
__device__ __forceinline__ void cp16(unsigned s, const void* g) {
    asm volatile("cp.async.cg.shared.global [%0], [%1], 16;" :: "r"(s), "l"(g) : "memory");
}
__device__ __forceinline__ void ldsm4(unsigned addr, unsigned* r) {
    asm volatile("ldmatrix.sync.aligned.m8n8.x4.shared.b16 {%0,%1,%2,%3}, [%4];"
                 : "=r"(r[0]), "=r"(r[1]), "=r"(r[2]), "=r"(r[3]) : "r"(addr));
}
__device__ __forceinline__ void mma16816(float* c, const unsigned* a,
                                         unsigned b0, unsigned b1) {
    asm volatile(
        "mma.sync.aligned.m16n8k16.row.col.f32.f16.f16.f32 "
        "{%0,%1,%2,%3}, {%4,%5,%6,%7}, {%8,%9}, {%0,%1,%2,%3};"
        : "+f"(c[0]), "+f"(c[1]), "+f"(c[2]), "+f"(c[3])
        : "r"(a[0]), "r"(a[1]), "r"(a[2]), "r"(a[3]), "r"(b0), "r"(b1));
}

// --------------------------- min/max kernels -------------------------------
__global__ void minmax_init(unsigned* mink, unsigned* maxk, int F) {
    int c = blockIdx.x * blockDim.x + threadIdx.x;
    if (c < F) { mink[c] = 0xFFFFFFFFu; maxk[c] = 0u; }
}
__global__ void colminmax(const float* __restrict__ X, int F, int chunk,
                          unsigned* mink, unsigned* maxk) {
    int c  = blockIdx.x * blockDim.x + threadIdx.x;
    int r0 = blockIdx.y * chunk;
    float lo =  3.402823466e38f, hi = -3.402823466e38f;
    const float* p = X + (size_t)r0 * F + c;
    #pragma unroll 1
    for (int r = 0; r < chunk; r += 8) {            // 8 independent loads -> MLP 8
        float v0 = p[(size_t)(r + 0) * F];
        float v1 = p[(size_t)(r + 1) * F];
        float v2 = p[(size_t)(r + 2) * F];
        float v3 = p[(size_t)(r + 3) * F];
        float v4 = p[(size_t)(r + 4) * F];
        float v5 = p[(size_t)(r + 5) * F];
        float v6 = p[(size_t)(r + 6) * F];
        float v7 = p[(size_t)(r + 7) * F];
        lo = fminf(lo, fminf(fminf(fminf(v0, v1), fminf(v2, v3)),
                             fminf(fminf(v4, v5), fminf(v6, v7))));
        hi = fmaxf(hi, fmaxf(fmaxf(fmaxf(v0, v1), fmaxf(v2, v3)),
                             fmaxf(fmaxf(v4, v5), fmaxf(v6, v7))));
    }
    atomicMin(&mink[c], fkey(lo));
    atomicMax(&maxk[c], fkey(hi));
}
__global__ void finalize_minmax(const unsigned* mink, const unsigned* maxk,
                                float* mn, float* sc, int F) {
    int c = blockIdx.x * blockDim.x + threadIdx.x;
    if (c < F) {
        float lo = funkey(mink[c]), hi = funkey(maxk[c]);
        mn[c] = lo; sc[c] = 2.0f / (hi - lo);
    }
}

// ------------------------------ bias reduce --------------------------------
// bias[o] = sum over chunk partials (partials produced inside prep_B)
__global__ void bias_reduce(const float* __restrict__ part,
                            float* __restrict__ bias, int nparts, int O) {
    int o = blockIdx.x * blockDim.x + threadIdx.x;
    float s0 = 0.0f, s1 = 0.0f, s2 = 0.0f, s3 = 0.0f;
    #pragma unroll 1
    for (int p = 0; p < nparts; p += 4) {           // 4 independent chains -> MLP 4
        s0 += part[(size_t)(p + 0) * O + o];
        s1 += part[(size_t)(p + 1) * O + o];
        s2 += part[(size_t)(p + 2) * O + o];
        s3 += part[(size_t)(p + 3) * O + o];
    }
    bias[o] = (s0 + s1) + (s2 + s3);
}

// ------------------------------ B prep -------------------------------------
// coeffs [F,O,9] fp32 -> per (nblock, 8-feature chunk): 18432B smem image.
// row n (0..127), col k (0..71): k<64 -> fp16(coeffs[f0+(k&7), n0+n, (k>>3)+1]).
// Also emits the chunk's d=0 partial bias sums (reuses staged data).
__global__ void prep_B(const float* __restrict__ coeffs,
                       unsigned* __restrict__ outB,
                       float* __restrict__ part, int F, int O) {
    __shared__ __align__(16) float stag[8 * 128 * 9];   // [il][n][d]
    const int nb = blockIdx.x, c = blockIdx.y, tid = threadIdx.x;
    const float* src = coeffs + ((size_t)(c * 8) * O + (size_t)nb * 128) * 9;
    // per-il blocks are 1152 contiguous floats and 16B-aligned -> float4 copy
    for (int idx4 = tid; idx4 < 2304; idx4 += 256) {
        int il = idx4 / 288, rem4 = idx4 - il * 288;
        reinterpret_cast<float4*>(stag)[idx4] =
            *reinterpret_cast<const float4*>(src + (size_t)il * O * 9 + rem4 * 4);
    }
    __syncthreads();
    const int nch = F / 8;
    unsigned* dst = outB + ((size_t)nb * nch + c) * TILE_U32;
    for (int j = tid; j < TILE_U32; j += 256) {
        int nn = j / 36;
        int k0 = (j - nn * 36) * 2;
        unsigned outv = 0;
        if (k0 < 64) {
            #pragma unroll
            for (int e = 0; e < 2; ++e) {
                int k  = k0 + e;
                int d  = (k >> 3) + 1;
                int il = k & 7;
                float v = stag[il * 1152 + nn * 9 + d];
                outv |= (unsigned)__half_as_ushort(__float2half_rn(v)) << (16 * e);
            }
        }
        dst[j] = outv;
    }
    // d=0 partial bias for this chunk's 128 outputs (fixed order, deterministic)
    if (tid < 128) {
        float s = 0.0f;
        #pragma unroll
        for (int il = 0; il < 8; ++il)
            s += stag[il * 1152 + tid * 9];
        part[(size_t)c * O + nb * 128 + tid] = s;
    }
}

// ------------------------- fused mma.sync GEMM -----------------------------
// C[128,128] per CTA = bias + sum over 8-feature chunks (K=64) of A(gen) x B.
// A double-buffered (gen overlapped with MMA), B triple-buffered cp.async.
// Optional fused per-column min/max atomics for the NEXT layer.
__global__ void __launch_bounds__(256, 2)
kan_mma(const float* __restrict__ X, const unsigned* __restrict__ gB,
        const float* __restrict__ mn, const float* __restrict__ sc,
        const float* __restrict__ bias, float* __restrict__ out,
        int F, int O, unsigned* mink2, unsigned* maxk2)
{
    extern __shared__ __align__(16) char smem[];
    const unsigned A_u = (unsigned)__cvta_generic_to_shared(smem);
    const unsigned B_u = A_u + 2 * TILE;                  // 3 stages after 2 A bufs
    __half* As = (__half*)smem;

    const int tid  = threadIdx.x;
    const int wid  = tid >> 5;
    const int lane = tid & 31;
    const int brow0 = blockIdx.y * 128;
    const int oc0   = blockIdx.x * 128;
    const int nch   = F / 8;
    const unsigned* gb = gB + (size_t)blockIdx.x * nch * TILE_U32;

    const int wm = (wid >> 2) * 64;
    const int wn = (wid & 3) * 32;
    const int lrow = ((lane >> 3) & 1) * 8 + (lane & 7);
    const int lcol = (lane >> 4) * 8;
    unsigned offA[4], offB[2];
    #pragma unroll
    for (int i = 0; i < 4; ++i) offA[i] = ((wm + i * 16 + lrow) * SA + lcol) * 2;
    #pragma unroll
    for (int t = 0; t < 2; ++t) offB[t] = ((wn + t * 16 + lrow) * SA + lcol) * 2;

    float acc[4][4][4];
    #pragma unroll
    for (int i = 0; i < 4; ++i)
        #pragma unroll
        for (int j = 0; j < 4; ++j)
            #pragma unroll
            for (int e = 0; e < 4; ++e) acc[i][j][e] = 0.0f;

    const int r  = tid >> 1;            // A-gen: row
    const int h4 = (tid & 1) << 2;      // A-gen: 4-feature half

    // ---- prologue: B(0), B(1) in flight; A(0) generated
    for (int idx = tid; idx < 1152; idx += 256)
        cp16(B_u + idx * 16, (const char*)gb + (size_t)idx * 16);
    asm volatile("cp.async.commit_group;" ::: "memory");
    for (int idx = tid; idx < 1152; idx += 256)
        cp16(B_u + TILE + idx * 16, (const char*)(gb + TILE_U32) + (size_t)idx * 16);
    asm volatile("cp.async.commit_group;" ::: "memory");
    {
        const float4 xv = *(const float4*)(X + (size_t)(brow0 + r) * F + h4);
        const float xs[4] = {xv.x, xv.y, xv.z, xv.w};
        unsigned* Arow = (unsigned*)(As + r * SA);
        #pragma unroll
        for (int p = 0; p < 2; ++p) {
            const int fl = h4 + 2 * p;
            float xa = (xs[2*p]   - __ldg(mn + fl))     * __ldg(sc + fl)     - 1.0f;
            float xb = (xs[2*p+1] - __ldg(mn + fl + 1)) * __ldg(sc + fl + 1) - 1.0f;
            float Ta = xa, Tb = xb, Pa = 1.0f, Pb = 1.0f;
            const float x2a = xa + xa, x2b = xb + xb;
            #pragma unroll
            for (int d = 1; d < 9; ++d) {
                Arow[(d - 1) * 4 + (fl >> 1)] =
                      (unsigned)__half_as_ushort(__float2half_rn(Ta))
                    | ((unsigned)__half_as_ushort(__float2half_rn(Tb)) << 16);
                float na = fmaf(x2a, Ta, -Pa);
                float nb = fmaf(x2b, Tb, -Pb);
                Pa = Ta; Pb = Tb; Ta = na; Tb = nb;
            }
        }
    }
    asm volatile("cp.async.wait_group 1;" ::: "memory");
    __syncthreads();

    int bstage = 0;                     // B stage of chunk c
    for (int c = 0; c < nch; ++c) {
        const unsigned Anow = A_u + ((unsigned)c & 1u) * TILE;
        const unsigned Bc   = B_u + (unsigned)bstage * TILE;

        // 1. issue B(c+2) into stage (bstage+2)%3
        const bool more = (c + 2 < nch);
        if (more) {
            int ns = bstage + 2; if (ns >= 3) ns -= 3;
            const char* gsrc = (const char*)(gb + (size_t)(c + 2) * TILE_U32);
            unsigned Bn = B_u + (unsigned)ns * TILE;
            for (int idx = tid; idx < 1152; idx += 256)
                cp16(Bn + idx * 16, gsrc + (size_t)idx * 16);
            asm volatile("cp.async.commit_group;" ::: "memory");
        }

        // 2. prefetch x for chunk c+1 (LDG latency overlaps MMAs below)
        float4 xv = make_float4(0.f, 0.f, 0.f, 0.f);
        const int f0n = (c + 1) * 8;
        if (c + 1 < nch)
            xv = *(const float4*)(X + (size_t)(brow0 + r) * F + f0n + h4);

        // 3. MMA: 4 slabs of K=16
        #pragma unroll
        for (int s = 0; s < 4; ++s) {
            const unsigned kh = (unsigned)(s * 32);
            unsigned a[4][4], b[2][4];
            #pragma unroll
            for (int i = 0; i < 4; ++i) ldsm4(Anow + offA[i] + kh, a[i]);
            #pragma unroll
            for (int t = 0; t < 2; ++t) ldsm4(Bc + offB[t] + kh, b[t]);
            #pragma unroll
            for (int i = 0; i < 4; ++i)
                #pragma unroll
                for (int t = 0; t < 2; ++t)
                    #pragma unroll
                    for (int nb = 0; nb < 2; ++nb)
                        mma16816(acc[i][t * 2 + nb], a[i], b[t][nb], b[t][nb + 2]);
        }

        // 4. expand A(c+1) into the other A buffer (tensor-shadow work)
        if (c + 1 < nch) {
            const float xs[4] = {xv.x, xv.y, xv.z, xv.w};
            unsigned* Arow = (unsigned*)(As + (((c + 1) & 1) * TILE / 2) + r * SA);
            #pragma unroll
            for (int p = 0; p < 2; ++p) {
                const int fl = h4 + 2 * p;
                const int f  = f0n + fl;
                float xa = (xs[2*p]   - __ldg(mn + f))     * __ldg(sc + f)     - 1.0f;
                float xb = (xs[2*p+1] - __ldg(mn + f + 1)) * __ldg(sc + f + 1) - 1.0f;
                float Ta = xa, Tb = xb, Pa = 1.0f, Pb = 1.0f;
                const float x2a = xa + xa, x2b = xb + xb;
                #pragma unroll
                for (int d = 1; d < 9; ++d) {
                    Arow[(d - 1) * 4 + (fl >> 1)] =
                          (unsigned)__half_as_ushort(__float2half_rn(Ta))
                        | ((unsigned)__half_as_ushort(__float2half_rn(Tb)) << 16);
                    float na = fmaf(x2a, Ta, -Pa);
                    float nb = fmaf(x2b, Tb, -Pb);
                    Pa = Ta; Pb = Tb; Ta = na; Tb = nb;
                }
            }
        }

        // 5. B(c+1) complete; everything visible
        if (more) asm volatile("cp.async.wait_group 1;" ::: "memory");
        else      asm volatile("cp.async.wait_group 0;" ::: "memory");
        __syncthreads();

        if (++bstage >= 3) bstage -= 3;
    }

    // ---- epilogue: + bias, store, fused next-layer column min/max
    #pragma unroll
    for (int j = 0; j < 4; ++j) {
        const int col = oc0 + wn + j * 8 + (lane & 3) * 2;
        const float2 bv = *(const float2*)(bias + col);
        float mnE =  3.402823466e38f, mxE = -3.402823466e38f;
        float mnO =  3.402823466e38f, mxO = -3.402823466e38f;
        #pragma unroll
        for (int i = 0; i < 4; ++i) {
            const int row0 = brow0 + wm + i * 16 + (lane >> 2);
            float2 vlo = {acc[i][j][0] + bv.x, acc[i][j][1] + bv.y};
            float2 vhi = {acc[i][j][2] + bv.x, acc[i][j][3] + bv.y};
            *(float2*)(out + (size_t)row0 * O + col)       = vlo;
            *(float2*)(out + (size_t)(row0 + 8) * O + col) = vhi;
            mnE = fminf(mnE, fminf(vlo.x, vhi.x));
            mxE = fmaxf(mxE, fmaxf(vlo.x, vhi.x));
            mnO = fminf(mnO, fminf(vlo.y, vhi.y));
            mxO = fmaxf(mxO, fmaxf(vlo.y, vhi.y));
        }
        if (mink2 != nullptr) {
            #pragma unroll
            for (int off = 4; off < 32; off <<= 1) {
                mnE = fminf(mnE, __shfl_xor_sync(0xFFFFFFFFu, mnE, off));
                mxE = fmaxf(mxE, __shfl_xor_sync(0xFFFFFFFFu, mxE, off));
                mnO = fminf(mnO, __shfl_xor_sync(0xFFFFFFFFu, mnO, off));
                mxO = fmaxf(mxO, __shfl_xor_sync(0xFFFFFFFFu, mxO, off));
            }
            if (lane < 4) {
                atomicMin(&mink2[col],     fkey(mnE));
                atomicMax(&maxk2[col],     fkey(mxE));
                atomicMin(&mink2[col + 1], fkey(mnO));
                atomicMax(&maxk2[col + 1], fkey(mxO));
            }
        }
    }
}

// ------------------------------ launcher -----------------------------------
extern "C" void kernel_launch(void* const* d_in, const int* in_sizes, int n_in,
                              void* d_out, int out_size) {
    const float* x  = (const float*)d_in[0];
    const float* c1 = (const float*)d_in[1];
    const float* c2 = (const float*)d_in[2];
    float* y = (float*)d_out;

    float *h, *mn, *sc, *bias1, *bias2, *bpart;
    unsigned *b1, *b2, *mk1, *xk1, *mk2, *xk2;
    cudaGetSymbolAddress((void**)&h,     g_h);
    cudaGetSymbolAddress((void**)&b1,    g_b1);
    cudaGetSymbolAddress((void**)&b2,    g_b2);
    cudaGetSymbolAddress((void**)&bias1, g_bias1);
    cudaGetSymbolAddress((void**)&bias2, g_bias2);
    cudaGetSymbolAddress((void**)&bpart, g_bpart);
    cudaGetSymbolAddress((void**)&mk1,   g_mk1);
    cudaGetSymbolAddress((void**)&xk1,   g_xk1);
    cudaGetSymbolAddress((void**)&mk2,   g_mk2);
    cudaGetSymbolAddress((void**)&xk2,   g_xk2);
    cudaGetSymbolAddress((void**)&mn,    g_mn);
    cudaGetSymbolAddress((void**)&sc,    g_sc);

    cudaFuncSetAttribute(kan_mma, cudaFuncAttributeMaxDynamicSharedMemorySize, 5 * TILE);

    // Fork a non-blocking side stream for coefficient prep. Created fresh per
    // call and intentionally leaked (host objects only, no device allocation;
    // kernel_launch is invoked a handful of times). Fork/join via events is the
    // documented graph-capture pattern.
    cudaStream_t s1;
    cudaStreamCreateWithFlags(&s1, cudaStreamNonBlocking);
    cudaEvent_t eFork, ePrep1, ePrep2;
    cudaEventCreateWithFlags(&eFork,  cudaEventDisableTiming);
    cudaEventCreateWithFlags(&ePrep1, cudaEventDisableTiming);
    cudaEventCreateWithFlags(&ePrep2, cudaEventDisableTiming);

    cudaEventRecord(eFork, 0);
    cudaStreamWaitEvent(s1, eFork, 0);

    // ---- side stream: packed B images (+fused d=0 partials), biases.
    // prep_B1/bias_red1 overlap the colminmax chain; prep_B2/bias_red2 overlap
    // GEMM1 (tensor-bound, DRAM idle; resources allow co-residency).
    prep_B<<<dim3(16, IN_DIM  / 8), 256, 0, s1>>>(c1, b1, bpart, IN_DIM, HID_DIM);
    bias_reduce<<<HID_DIM / 256, 256, 0, s1>>>(bpart, bias1, IN_DIM / 8, HID_DIM);
    cudaEventRecord(ePrep1, s1);
    prep_B<<<dim3(8,  HID_DIM / 8), 256, 0, s1>>>(c2, b2, bpart, HID_DIM, OUT_DIM);
    bias_reduce<<<OUT_DIM / 256, 256, 0, s1>>>(bpart, bias2, HID_DIM / 8, OUT_DIM);
    cudaEventRecord(ePrep2, s1);

    // ---- main stream: layer-1 normalization stats (independent of coeffs)
    minmax_init<<<IN_DIM / 256, 256>>>(mk1, xk1, IN_DIM);
    colminmax<<<dim3(IN_DIM / 256, BATCH / 256), 256>>>(x, IN_DIM, 256, mk1, xk1);
    finalize_minmax<<<IN_DIM / 256, 256>>>(mk1, xk1, mn, sc, IN_DIM);
    minmax_init<<<HID_DIM / 256, 256>>>(mk2, xk2, HID_DIM);   // for fused epilogue

    // ---- layer 1 (needs b1/bias1 from side stream)
    cudaStreamWaitEvent(0, ePrep1, 0);
    kan_mma<<<dim3(HID_DIM / 128, BATCH / 128), 256, 5 * TILE>>>(
        x, b1, mn, sc, bias1, h, IN_DIM, HID_DIM, mk2, xk2);

    // ---- layer 2 (minmax from fused epilogue; waits b2/bias2 join)
    finalize_minmax<<<HID_DIM / 256, 256>>>(mk2, xk2, mn, sc, HID_DIM);
    cudaStreamWaitEvent(0, ePrep2, 0);
    kan_mma<<<dim3(OUT_DIM / 128, BATCH / 128), 256, 5 * TILE>>>(
        h, b2, mn, sc, bias2, y, HID_DIM, OUT_DIM, nullptr, nullptr);
}

// round 17
// speedup vs baseline: 6.5000x; 1.0016x over previous
#include <cuda_runtime.h>
#include <cuda_fp16.h>
#include <cstdint>

#define BATCH   16384
#define IN_DIM  1024
#define HID_DIM 2048
#define OUT_DIM 1024

#define SA        72                  // k-stride (fp16): 64 data + 8 pad, 144B rows
#define TILE      18432               // one operand tile: 128 x SA x 2B
#define TILE_U32  4608

// ------------------------------ scratch ------------------------------------
__device__ float    g_h [(size_t)BATCH * HID_DIM];
__device__ unsigned g_b1[(size_t)16 * 128 * TILE_U32];   // layer1 packed B images
__device__ unsigned g_b2[(size_t)8  * 256 * TILE_U32];   // layer2 packed B images
__device__ float    g_bias1[HID_DIM], g_bias2[OUT_DIM];
__device__ float    g_bpart[262144];                     // chunk-partial d=0 sums
__device__ unsigned g_mk1[HID_DIM], g_xk1[HID_DIM];      // layer1 input minmax
__device__ unsigned g_mk2[HID_DIM], g_xk2[HID_DIM];      // layer2 (fused) minmax
__device__ float    g_mn[HID_DIM],  g_sc[HID_DIM];
__device__ unsigned g_done;                              // colminmax last-block ctr

// ---------------------------- helpers --------------------------------------
__device__ __forceinline__ unsigned fkey(float f) {
    unsigned u = __float_as_uint(f);
    return (u & 0x80000000u) ? ~u : (u | 0x80000000u);
}
__device__ __forceinline__ float funkey(unsigned u) {
    return __uint_as_float((u & 0x80000000u) ? (u ^ 0x80000000u) : ~u);
}
__device__ __forceinline__ void cp16(unsigned s, const void* g) {
    asm volatile("cp.async.cg.shared.global [%0], [%1], 16;" :: "r"(s), "l"(g) : "memory");
}
__device__ __forceinline__ void ldsm4(unsigned addr, unsigned* r) {
    asm volatile("ldmatrix.sync.aligned.m8n8.x4.shared.b16 {%0,%1,%2,%3}, [%4];"
                 : "=r"(r[0]), "=r"(r[1]), "=r"(r[2]), "=r"(r[3]) : "r"(addr));
}
__device__ __forceinline__ void mma16816(float* c, const unsigned* a,
                                         unsigned b0, unsigned b1) {
    asm volatile(
        "mma.sync.aligned.m16n8k16.row.col.f32.f16.f16.f32 "
        "{%0,%1,%2,%3}, {%4,%5,%6,%7}, {%8,%9}, {%0,%1,%2,%3};"
        : "+f"(c[0]), "+f"(c[1]), "+f"(c[2]), "+f"(c[3])
        : "r"(a[0]), "r"(a[1]), "r"(a[2]), "r"(a[3]), "r"(b0), "r"(b1));
}

// --------------------------- min/max kernels -------------------------------
// init BOTH layers' key arrays in one launch (grid = HID_DIM/256)
__global__ void minmax_init_all(unsigned* mk1, unsigned* xk1,
                                unsigned* mk2, unsigned* xk2) {
    int c = blockIdx.x * blockDim.x + threadIdx.x;
    mk2[c] = 0xFFFFFFFFu; xk2[c] = 0u;
    if (c < IN_DIM) { mk1[c] = 0xFFFFFFFFu; xk1[c] = 0u; }
}

// column min/max + fused finalize: last block (atomic counter) computes mn/sc.
__global__ void colminmax_fin(const float* __restrict__ X, int F, int chunk,
                              unsigned* mink, unsigned* maxk,
                              float* __restrict__ mn, float* __restrict__ sc,
                              int nblocks) {
    int c  = blockIdx.x * blockDim.x + threadIdx.x;
    int r0 = blockIdx.y * chunk;
    float lo =  3.402823466e38f, hi = -3.402823466e38f;
    const float* p = X + (size_t)r0 * F + c;
    #pragma unroll 1
    for (int r = 0; r < chunk; r += 8) {            // 8 independent loads -> MLP 8
        float v0 = p[(size_t)(r + 0) * F];
        float v1 = p[(size_t)(r + 1) * F];
        float v2 = p[(size_t)(r + 2) * F];
        float v3 = p[(size_t)(r + 3) * F];
        float v4 = p[(size_t)(r + 4) * F];
        float v5 = p[(size_t)(r + 5) * F];
        float v6 = p[(size_t)(r + 6) * F];
        float v7 = p[(size_t)(r + 7) * F];
        lo = fminf(lo, fminf(fminf(fminf(v0, v1), fminf(v2, v3)),
                             fminf(fminf(v4, v5), fminf(v6, v7))));
        hi = fmaxf(hi, fmaxf(fmaxf(fmaxf(v0, v1), fmaxf(v2, v3)),
                             fmaxf(fmaxf(v4, v5), fmaxf(v6, v7))));
    }
    atomicMin(&mink[c], fkey(lo));
    atomicMax(&maxk[c], fkey(hi));

    // last-block-done: finalize mn/sc once all blocks' atomics are visible
    __threadfence();
    __shared__ int is_last;
    if (threadIdx.x == 0)
        is_last = (atomicAdd(&g_done, 1u) == (unsigned)(nblocks - 1));
    __syncthreads();
    if (is_last) {
        for (int f = threadIdx.x; f < F; f += blockDim.x) {
            float l = funkey(mink[f]), h2 = funkey(maxk[f]);
            mn[f] = l; sc[f] = 2.0f / (h2 - l);
        }
        if (threadIdx.x == 0) g_done = 0;           // reset for graph replay
    }
}

__global__ void finalize_minmax(const unsigned* mink, const unsigned* maxk,
                                float* mn, float* sc, int F) {
    int c = blockIdx.x * blockDim.x + threadIdx.x;
    if (c < F) {
        float lo = funkey(mink[c]), hi = funkey(maxk[c]);
        mn[c] = lo; sc[c] = 2.0f / (hi - lo);
    }
}

// ------------------------------ bias reduce --------------------------------
__global__ void bias_reduce(const float* __restrict__ part,
                            float* __restrict__ bias, int nparts, int O) {
    int o = blockIdx.x * blockDim.x + threadIdx.x;
    float s0 = 0.0f, s1 = 0.0f, s2 = 0.0f, s3 = 0.0f;
    #pragma unroll 1
    for (int p = 0; p < nparts; p += 4) {
        s0 += part[(size_t)(p + 0) * O + o];
        s1 += part[(size_t)(p + 1) * O + o];
        s2 += part[(size_t)(p + 2) * O + o];
        s3 += part[(size_t)(p + 3) * O + o];
    }
    bias[o] = (s0 + s1) + (s2 + s3);
}

// ------------------------------ B prep -------------------------------------
// coeffs [F,O,9] fp32 -> per (nblock, 8-feature chunk): 18432B smem image.
// row n (0..127), col k (0..71): k<64 -> fp16(coeffs[f0+(k&7), n0+n, (k>>3)+1]).
// Also emits the chunk's d=0 partial bias sums (reuses staged data).
__global__ void prep_B(const float* __restrict__ coeffs,
                       unsigned* __restrict__ outB,
                       float* __restrict__ part, int F, int O) {
    __shared__ __align__(16) float stag[8 * 128 * 9];   // [il][n][d]
    const int nb = blockIdx.x, c = blockIdx.y, tid = threadIdx.x;
    const float* src = coeffs + ((size_t)(c * 8) * O + (size_t)nb * 128) * 9;
    for (int idx4 = tid; idx4 < 2304; idx4 += 256) {
        int il = idx4 / 288, rem4 = idx4 - il * 288;
        reinterpret_cast<float4*>(stag)[idx4] =
            *reinterpret_cast<const float4*>(src + (size_t)il * O * 9 + rem4 * 4);
    }
    __syncthreads();
    const int nch = F / 8;
    unsigned* dst = outB + ((size_t)nb * nch + c) * TILE_U32;
    for (int j = tid; j < TILE_U32; j += 256) {
        int nn = j / 36;
        int k0 = (j - nn * 36) * 2;
        unsigned outv = 0;
        if (k0 < 64) {
            #pragma unroll
            for (int e = 0; e < 2; ++e) {
                int k  = k0 + e;
                int d  = (k >> 3) + 1;
                int il = k & 7;
                float v = stag[il * 1152 + nn * 9 + d];
                outv |= (unsigned)__half_as_ushort(__float2half_rn(v)) << (16 * e);
            }
        }
        dst[j] = outv;
    }
    if (tid < 128) {
        float s = 0.0f;
        #pragma unroll
        for (int il = 0; il < 8; ++il)
            s += stag[il * 1152 + tid * 9];
        part[(size_t)c * O + nb * 128 + tid] = s;
    }
}

// ------------------------- fused mma.sync GEMM -----------------------------
// C[128,128] per CTA = bias + sum over 8-feature chunks (K=64) of A(gen) x B.
// A double-buffered (gen overlapped with MMA), B triple-buffered cp.async.
// Optional fused per-column min/max atomics for the NEXT layer.
__global__ void __launch_bounds__(256, 2)
kan_mma(const float* __restrict__ X, const unsigned* __restrict__ gB,
        const float* __restrict__ mn, const float* __restrict__ sc,
        const float* __restrict__ bias, float* __restrict__ out,
        int F, int O, unsigned* mink2, unsigned* maxk2)
{
    extern __shared__ __align__(16) char smem[];
    const unsigned A_u = (unsigned)__cvta_generic_to_shared(smem);
    const unsigned B_u = A_u + 2 * TILE;                  // 3 stages after 2 A bufs
    __half* As = (__half*)smem;

    const int tid  = threadIdx.x;
    const int wid  = tid >> 5;
    const int lane = tid & 31;
    const int brow0 = blockIdx.y * 128;
    const int oc0   = blockIdx.x * 128;
    const int nch   = F / 8;
    const unsigned* gb = gB + (size_t)blockIdx.x * nch * TILE_U32;

    const int wm = (wid >> 2) * 64;
    const int wn = (wid & 3) * 32;
    const int lrow = ((lane >> 3) & 1) * 8 + (lane & 7);
    const int lcol = (lane >> 4) * 8;
    unsigned offA[4], offB[2];
    #pragma unroll
    for (int i = 0; i < 4; ++i) offA[i] = ((wm + i * 16 + lrow) * SA + lcol) * 2;
    #pragma unroll
    for (int t = 0; t < 2; ++t) offB[t] = ((wn + t * 16 + lrow) * SA + lcol) * 2;

    float acc[4][4][4];
    #pragma unroll
    for (int i = 0; i < 4; ++i)
        #pragma unroll
        for (int j = 0; j < 4; ++j)
            #pragma unroll
            for (int e = 0; e < 4; ++e) acc[i][j][e] = 0.0f;

    const int r  = tid >> 1;            // A-gen: row
    const int h4 = (tid & 1) << 2;      // A-gen: 4-feature half

    // ---- prologue: B(0), B(1) in flight; A(0) generated
    for (int idx = tid; idx < 1152; idx += 256)
        cp16(B_u + idx * 16, (const char*)gb + (size_t)idx * 16);
    asm volatile("cp.async.commit_group;" ::: "memory");
    for (int idx = tid; idx < 1152; idx += 256)
        cp16(B_u + TILE + idx * 16, (const char*)(gb + TILE_U32) + (size_t)idx * 16);
    asm volatile("cp.async.commit_group;" ::: "memory");
    {
        const float4 xv = *(const float4*)(X + (size_t)(brow0 + r) * F + h4);
        const float xs[4] = {xv.x, xv.y, xv.z, xv.w};
        unsigned* Arow = (unsigned*)(As + r * SA);
        #pragma unroll
        for (int p = 0; p < 2; ++p) {
            const int fl = h4 + 2 * p;
            float xa = (xs[2*p]   - __ldg(mn + fl))     * __ldg(sc + fl)     - 1.0f;
            float xb = (xs[2*p+1] - __ldg(mn + fl + 1)) * __ldg(sc + fl + 1) - 1.0f;
            float Ta = xa, Tb = xb, Pa = 1.0f, Pb = 1.0f;
            const float x2a = xa + xa, x2b = xb + xb;
            #pragma unroll
            for (int d = 1; d < 9; ++d) {
                Arow[(d - 1) * 4 + (fl >> 1)] =
                      (unsigned)__half_as_ushort(__float2half_rn(Ta))
                    | ((unsigned)__half_as_ushort(__float2half_rn(Tb)) << 16);
                float na = fmaf(x2a, Ta, -Pa);
                float nb = fmaf(x2b, Tb, -Pb);
                Pa = Ta; Pb = Tb; Ta = na; Tb = nb;
            }
        }
    }
    asm volatile("cp.async.wait_group 1;" ::: "memory");
    __syncthreads();

    int bstage = 0;                     // B stage of chunk c
    for (int c = 0; c < nch; ++c) {
        const unsigned Anow = A_u + ((unsigned)c & 1u) * TILE;
        const unsigned Bc   = B_u + (unsigned)bstage * TILE;

        // 1. issue B(c+2) into stage (bstage+2)%3
        const bool more = (c + 2 < nch);
        if (more) {
            int ns = bstage + 2; if (ns >= 3) ns -= 3;
            const char* gsrc = (const char*)(gb + (size_t)(c + 2) * TILE_U32);
            unsigned Bn = B_u + (unsigned)ns * TILE;
            for (int idx = tid; idx < 1152; idx += 256)
                cp16(Bn + idx * 16, gsrc + (size_t)idx * 16);
            asm volatile("cp.async.commit_group;" ::: "memory");
        }

        // 2. prefetch x for chunk c+1 (LDG latency overlaps MMAs below)
        float4 xv = make_float4(0.f, 0.f, 0.f, 0.f);
        const int f0n = (c + 1) * 8;
        if (c + 1 < nch)
            xv = *(const float4*)(X + (size_t)(brow0 + r) * F + f0n + h4);

        // 3. MMA: 4 slabs of K=16
        #pragma unroll
        for (int s = 0; s < 4; ++s) {
            const unsigned kh = (unsigned)(s * 32);
            unsigned a[4][4], b[2][4];
            #pragma unroll
            for (int i = 0; i < 4; ++i) ldsm4(Anow + offA[i] + kh, a[i]);
            #pragma unroll
            for (int t = 0; t < 2; ++t) ldsm4(Bc + offB[t] + kh, b[t]);
            #pragma unroll
            for (int i = 0; i < 4; ++i)
                #pragma unroll
                for (int t = 0; t < 2; ++t)
                    #pragma unroll
                    for (int nb = 0; nb < 2; ++nb)
                        mma16816(acc[i][t * 2 + nb], a[i], b[t][nb], b[t][nb + 2]);
        }

        // 4. expand A(c+1) into the other A buffer (tensor-shadow work)
        if (c + 1 < nch) {
            const float xs[4] = {xv.x, xv.y, xv.z, xv.w};
            unsigned* Arow = (unsigned*)(As + (((c + 1) & 1) * TILE / 2) + r * SA);
            #pragma unroll
            for (int p = 0; p < 2; ++p) {
                const int fl = h4 + 2 * p;
                const int f  = f0n + fl;
                float xa = (xs[2*p]   - __ldg(mn + f))     * __ldg(sc + f)     - 1.0f;
                float xb = (xs[2*p+1] - __ldg(mn + f + 1)) * __ldg(sc + f + 1) - 1.0f;
                float Ta = xa, Tb = xb, Pa = 1.0f, Pb = 1.0f;
                const float x2a = xa + xa, x2b = xb + xb;
                #pragma unroll
                for (int d = 1; d < 9; ++d) {
                    Arow[(d - 1) * 4 + (fl >> 1)] =
                          (unsigned)__half_as_ushort(__float2half_rn(Ta))
                        | ((unsigned)__half_as_ushort(__float2half_rn(Tb)) << 16);
                    float na = fmaf(x2a, Ta, -Pa);
                    float nb = fmaf(x2b, Tb, -Pb);
                    Pa = Ta; Pb = Tb; Ta = na; Tb = nb;
                }
            }
        }

        // 5. B(c+1) complete; everything visible
        if (more) asm volatile("cp.async.wait_group 1;" ::: "memory");
        else      asm volatile("cp.async.wait_group 0;" ::: "memory");
        __syncthreads();

        if (++bstage >= 3) bstage -= 3;
    }

    // ---- epilogue: + bias, store, fused next-layer column min/max
    #pragma unroll
    for (int j = 0; j < 4; ++j) {
        const int col = oc0 + wn + j * 8 + (lane & 3) * 2;
        const float2 bv = *(const float2*)(bias + col);
        float mnE =  3.402823466e38f, mxE = -3.402823466e38f;
        float mnO =  3.402823466e38f, mxO = -3.402823466e38f;
        #pragma unroll
        for (int i = 0; i < 4; ++i) {
            const int row0 = brow0 + wm + i * 16 + (lane >> 2);
            float2 vlo = {acc[i][j][0] + bv.x, acc[i][j][1] + bv.y};
            float2 vhi = {acc[i][j][2] + bv.x, acc[i][j][3] + bv.y};
            *(float2*)(out + (size_t)row0 * O + col)       = vlo;
            *(float2*)(out + (size_t)(row0 + 8) * O + col) = vhi;
            mnE = fminf(mnE, fminf(vlo.x, vhi.x));
            mxE = fmaxf(mxE, fmaxf(vlo.x, vhi.x));
            mnO = fminf(mnO, fminf(vlo.y, vhi.y));
            mxO = fmaxf(mxO, fmaxf(vlo.y, vhi.y));
        }
        if (mink2 != nullptr) {
            #pragma unroll
            for (int off = 4; off < 32; off <<= 1) {
                mnE = fminf(mnE, __shfl_xor_sync(0xFFFFFFFFu, mnE, off));
                mxE = fmaxf(mxE, __shfl_xor_sync(0xFFFFFFFFu, mxE, off));
                mnO = fminf(mnO, __shfl_xor_sync(0xFFFFFFFFu, mnO, off));
                mxO = fmaxf(mxO, __shfl_xor_sync(0xFFFFFFFFu, mxO, off));
            }
            if (lane < 4) {
                atomicMin(&mink2[col],     fkey(mnE));
                atomicMax(&maxk2[col],     fkey(mxE));
                atomicMin(&mink2[col + 1], fkey(mnO));
                atomicMax(&maxk2[col + 1], fkey(mxO));
            }
        }
    }
}

// ------------------------------ launcher -----------------------------------
extern "C" void kernel_launch(void* const* d_in, const int* in_sizes, int n_in,
                              void* d_out, int out_size) {
    const float* x  = (const float*)d_in[0];
    const float* c1 = (const float*)d_in[1];
    const float* c2 = (const float*)d_in[2];
    float* y = (float*)d_out;

    float *h, *mn, *sc, *bias1, *bias2, *bpart;
    unsigned *b1, *b2, *mk1, *xk1, *mk2, *xk2;
    cudaGetSymbolAddress((void**)&h,     g_h);
    cudaGetSymbolAddress((void**)&b1,    g_b1);
    cudaGetSymbolAddress((void**)&b2,    g_b2);
    cudaGetSymbolAddress((void**)&bias1, g_bias1);
    cudaGetSymbolAddress((void**)&bias2, g_bias2);
    cudaGetSymbolAddress((void**)&bpart, g_bpart);
    cudaGetSymbolAddress((void**)&mk1,   g_mk1);
    cudaGetSymbolAddress((void**)&xk1,   g_xk1);
    cudaGetSymbolAddress((void**)&mk2,   g_mk2);
    cudaGetSymbolAddress((void**)&xk2,   g_xk2);
    cudaGetSymbolAddress((void**)&mn,    g_mn);
    cudaGetSymbolAddress((void**)&sc,    g_sc);

    cudaFuncSetAttribute(kan_mma, cudaFuncAttributeMaxDynamicSharedMemorySize, 5 * TILE);

    // Fork a non-blocking side stream for coefficient prep (host objects only,
    // intentionally leaked; fork/join via events is the documented capture pattern).
    cudaStream_t s1;
    cudaStreamCreateWithFlags(&s1, cudaStreamNonBlocking);
    cudaEvent_t eFork, ePrep1, ePrep2;
    cudaEventCreateWithFlags(&eFork,  cudaEventDisableTiming);
    cudaEventCreateWithFlags(&ePrep1, cudaEventDisableTiming);
    cudaEventCreateWithFlags(&ePrep2, cudaEventDisableTiming);

    cudaEventRecord(eFork, 0);
    cudaStreamWaitEvent(s1, eFork, 0);

    // ---- side stream: packed B images (+fused d=0 partials), biases.
    prep_B<<<dim3(16, IN_DIM  / 8), 256, 0, s1>>>(c1, b1, bpart, IN_DIM, HID_DIM);
    bias_reduce<<<HID_DIM / 256, 256, 0, s1>>>(bpart, bias1, IN_DIM / 8, HID_DIM);
    cudaEventRecord(ePrep1, s1);
    prep_B<<<dim3(8,  HID_DIM / 8), 256, 0, s1>>>(c2, b2, bpart, HID_DIM, OUT_DIM);
    bias_reduce<<<OUT_DIM / 256, 256, 0, s1>>>(bpart, bias2, HID_DIM / 8, OUT_DIM);
    cudaEventRecord(ePrep2, s1);

    // ---- main stream: layer-1 stats, 2 launches instead of 4
    minmax_init_all<<<HID_DIM / 256, 256>>>(mk1, xk1, mk2, xk2);
    colminmax_fin<<<dim3(IN_DIM / 256, BATCH / 256), 256>>>(
        x, IN_DIM, 256, mk1, xk1, mn, sc,
        (IN_DIM / 256) * (BATCH / 256));

    // ---- layer 1 (needs b1/bias1 from side stream)
    cudaStreamWaitEvent(0, ePrep1, 0);
    kan_mma<<<dim3(HID_DIM / 128, BATCH / 128), 256, 5 * TILE>>>(
        x, b1, mn, sc, bias1, h, IN_DIM, HID_DIM, mk2, xk2);

    // ---- layer 2 (minmax from fused epilogue; waits b2/bias2 join)
    finalize_minmax<<<HID_DIM / 256, 256>>>(mk2, xk2, mn, sc, HID_DIM);
    cudaStreamWaitEvent(0, ePrep2, 0);
    kan_mma<<<dim3(OUT_DIM / 128, BATCH / 128), 256, 5 * TILE>>>(
        h, b2, mn, sc, bias2, y, HID_DIM, OUT_DIM, nullptr, nullptr);
}